// round 7
// baseline (speedup 1.0000x reference)
#include <cuda_runtime.h>
#include <math.h>
#include <cstdint>

// Problem constants
#define BB 2
#define SS 2048
#define EE 1024
#define HH 16
#define HD 64
#define BH (BB*HH)
#define SCALE 0.125f   // 1/sqrt(64)

#define ST 68    // smem row stride (words) for permuted operand tiles

// Scratch (allocation-free rule: __device__ globals)
static __device__ float g_q  [(size_t)BH*SS*64];   // (bh, s, d)        fp32
static __device__ float g_kp [(size_t)BH*SS*64];   // (bh, s, pk(d))    tf32-rounded
static __device__ float g_vp [(size_t)BH*64*SS];   // (bh, v, tilePerm(s)) tf32-rounded
static __device__ float g_attp[(size_t)BB*SS*EE];  // (b, s, h*64+pk(c)) tf32-rounded
static __device__ float g_wop[(size_t)EE*EE];      // (e_out, blk64perm(e_in)) tf32-rounded

// ---------------------------------------------------------------------------
// helpers
// ---------------------------------------------------------------------------
__device__ __forceinline__ uint32_t f2tf32(float x) {
    uint32_t r;
    asm("cvt.rna.tf32.f32 %0, %1;" : "=r"(r) : "f"(x));
    return r;
}
__device__ __forceinline__ float frna(float x) { return __uint_as_float(f2tf32(x)); }
__device__ __forceinline__ int pk64(int k) { return (k & 3)*16 + (k >> 2); }

// D(16x8) += A(16x8) * B(8x8)
__device__ __forceinline__ void mma_tf32(float c[4], float a0, float a1,
                                         float a2, float a3, float b0, float b1) {
    asm volatile(
        "mma.sync.aligned.m16n8k8.row.col.f32.tf32.tf32.f32 "
        "{%0,%1,%2,%3}, {%4,%5,%6,%7}, {%8,%9}, {%0,%1,%2,%3};"
        : "+f"(c[0]), "+f"(c[1]), "+f"(c[2]), "+f"(c[3])
        : "r"(__float_as_uint(a0)), "r"(__float_as_uint(a1)),
          "r"(__float_as_uint(a2)), "r"(__float_as_uint(a3)),
          "r"(__float_as_uint(b0)), "r"(__float_as_uint(b1)));
}

// ---------------------------------------------------------------------------
// Kernel 0: Wo pre-pass.  g_wop[n][blk64(k) + pk64(k%64)] = rna(Wo[k][n])
// Tile: k 64 x n 32, smem transpose, coalesced both sides.
// ---------------------------------------------------------------------------
__global__ __launch_bounds__(256) void wo_prep(const float* __restrict__ Wo)
{
    __shared__ float t[64][33];
    int k0 = blockIdx.x * 64, n0 = blockIdx.y * 32;
    int tx = threadIdx.x & 31, ty = threadIdx.x >> 5;

    for (int i = ty; i < 64; i += 8)
        t[i][tx] = Wo[(size_t)(k0 + i)*EE + n0 + tx];
    __syncthreads();
    for (int i = ty; i < 32; i += 8) {
        int x0 = tx, x1 = tx + 32;                 // output cols within 64-block
        g_wop[(size_t)(n0 + i)*EE + k0 + x0] = frna(t[4*(x0 & 15) + (x0 >> 4)][i]);
        g_wop[(size_t)(n0 + i)*EE + k0 + x1] = frna(t[4*(x1 & 15) + (x1 >> 4)][i]);
    }
}

// ---------------------------------------------------------------------------
// Kernel 1: QKV projection on tf32 mma.
// CTA = (bh, 128-row s tile), 256 threads = 8 warps x 16 rows.
// Outputs: Q natural fp32 | K permuted+rounded (s, pk(d)) |
//          V rounded, v-major with within-64-tile permuted s.
// ---------------------------------------------------------------------------
#define AST 68
#define BST 72
#define QKV_SMEM_FLOATS (128*AST + 3*64*BST)
#define QKV_SMEM_BYTES  (QKV_SMEM_FLOATS*4)

__global__ __launch_bounds__(256) void qkv_mma_kernel(
    const float* __restrict__ x,
    const float* __restrict__ Wq, const float* __restrict__ bq,
    const float* __restrict__ Wk, const float* __restrict__ bk,
    const float* __restrict__ Wv, const float* __restrict__ bv)
{
    extern __shared__ __align__(16) float smf[];
    float* At = smf;                 // [m=128][k=64] stride AST
    float* Ws = smf + 128*AST;       // 3 x [k=64][n=64] stride BST

    int tid  = threadIdx.x;
    int lane = tid & 31;
    int warp = tid >> 5;
    int g = lane >> 2, q = lane & 3;

    int bh = blockIdx.x; int b = bh >> 4, h = bh & 15;
    int s0 = blockIdx.y * 128;
    int wm = warp * 16;

    for (int idx = tid; idx < 2048; idx += 256) {
        int row = idx >> 4, c4 = (idx & 15) * 4;
        *(float4*)&At[row*AST + c4] = *(const float4*)&x[((size_t)b*SS + s0 + row)*EE + h*HD + c4];
    }
    const float* Wp[3] = {Wq, Wk, Wv};
    for (int w = 0; w < 3; ++w)
        for (int idx = tid; idx < 1024; idx += 256) {
            int row = idx >> 4, c4 = (idx & 15) * 4;
            *(float4*)&Ws[w*64*BST + row*BST + c4] = *(const float4*)&Wp[w][(size_t)row*64 + c4];
        }
    __syncthreads();

    int r0g = s0 + wm + g, r1g = s0 + wm + g + 8;
    int sr0 = (r0g & ~63) + pk64(r0g & 63);       // permuted s index for V
    int sr1 = (r1g & ~63) + pk64(r1g & 63);

    const float* bp[3] = {bq, bk, bv};
    for (int w = 0; w < 3; ++w) {
        float acc[8][4] = {};
        const float* B = &Ws[w*64*BST];
        #pragma unroll
        for (int kk = 0; kk < 8; ++kk) {
            float a0 = At[(wm + g    )*AST + kk*8 + q    ];
            float a1 = At[(wm + g + 8)*AST + kk*8 + q    ];
            float a2 = At[(wm + g    )*AST + kk*8 + q + 4];
            float a3 = At[(wm + g + 8)*AST + kk*8 + q + 4];
            a0 = frna(a0); a1 = frna(a1); a2 = frna(a2); a3 = frna(a3);
            #pragma unroll
            for (int nb = 0; nb < 8; ++nb) {
                float b0 = frna(B[(kk*8 + q    )*BST + nb*8 + g]);
                float b1 = frna(B[(kk*8 + q + 4)*BST + nb*8 + g]);
                mma_tf32(acc[nb], a0, a1, a2, a3, b0, b1);
            }
        }

        #pragma unroll
        for (int nb = 0; nb < 8; ++nb) {
            int c = nb*8 + 2*q;
            float bb0 = bp[w][c], bb1 = bp[w][c + 1];
            float v00 = acc[nb][0] + bb0, v01 = acc[nb][1] + bb1;
            float v10 = acc[nb][2] + bb0, v11 = acc[nb][3] + bb1;
            if (w == 0) {
                float* o = &g_q[((size_t)bh*SS)*64];
                o[(size_t)r0g*64 + c] = v00; o[(size_t)r0g*64 + c + 1] = v01;
                o[(size_t)r1g*64 + c] = v10; o[(size_t)r1g*64 + c + 1] = v11;
            } else if (w == 1) {
                int pc = pk64(c);                 // pk64(c+1) == pc+16 (c even)
                float* o = &g_kp[((size_t)bh*SS)*64];
                o[(size_t)r0g*64 + pc]      = frna(v00);
                o[(size_t)r0g*64 + pc + 16] = frna(v01);
                o[(size_t)r1g*64 + pc]      = frna(v10);
                o[(size_t)r1g*64 + pc + 16] = frna(v11);
            } else {
                float* o = &g_vp[(size_t)bh*64*SS];
                o[(size_t)c*SS + sr0]       = frna(v00);
                o[(size_t)(c + 1)*SS + sr0] = frna(v01);
                o[(size_t)c*SS + sr1]       = frna(v10);
                o[(size_t)(c + 1)*SS + sr1] = frna(v11);
            }
        }
    }
}

// ---------------------------------------------------------------------------
// Kernel 2: attention.  CTA = (bh, 128 q-rows), 256 threads = 8 warps.
// All operands pre-permuted + pre-rounded; inner loop = LDS.128 + HMMA + exp.
// QK 1x, PV 1x (rna).  No-max softmax; one divide at the end.
// ---------------------------------------------------------------------------
#define ATTN_SMEM_FLOATS (2*64*ST + 8*16*ST)
#define ATTN_SMEM_BYTES  (ATTN_SMEM_FLOATS*4)

__global__ __launch_bounds__(256, 2) void attn_mma_kernel(const float* __restrict__ mask)
{
    extern __shared__ __align__(16) float smf[];
    float* Kp = smf;                    // [n=s_loc][pk(d)]
    float* Vp = smf + 64*ST;            // [n=v][pk(s_loc)]
    float* Pp = smf + 2*64*ST + (threadIdx.x >> 5)*(16*ST);   // [m][pk(s_loc)]

    int tid = threadIdx.x;
    int lane = tid & 31;
    int warp = tid >> 5;
    int g = lane >> 2, q = lane & 3;

    int bh = blockIdx.x, b = bh >> 4, h = bh & 15;
    int q0 = blockIdx.y * 128;
    int wr = q0 + warp * 16;

    // Q fragments (SCALE folded, rna)
    float aq[8][4];
    {
        const float* qb = &g_q[((size_t)bh*SS + wr)*64];
        #pragma unroll
        for (int kk = 0; kk < 8; ++kk) {
            aq[kk][0] = frna(qb[(size_t)g      *64 + kk*8 + q    ] * SCALE);
            aq[kk][1] = frna(qb[(size_t)(g + 8)*64 + kk*8 + q    ] * SCALE);
            aq[kk][2] = frna(qb[(size_t)g      *64 + kk*8 + q + 4] * SCALE);
            aq[kk][3] = frna(qb[(size_t)(g + 8)*64 + kk*8 + q + 4] * SCALE);
        }
    }

    float oacc[8][4] = {};
    float lsum0 = 0.f, lsum1 = 0.f;
    const float* mrow0 = &mask[(size_t)(wr + g    )*SS];
    const float* mrow1 = &mask[(size_t)(wr + g + 8)*SS];
    int pc0 = 16*((2*q) & 3) + (q >> 1);   // pk col base for c = 8nb+2q (add 2nb)

    for (int jt = 0; jt < SS/64; ++jt) {
        int s0 = jt * 64;
        __syncthreads();
        for (int idx = tid; idx < 1024; idx += 256) {
            int row = idx >> 4, c4 = (idx & 15) * 4;
            *(float4*)&Kp[row*ST + c4] = *(const float4*)&g_kp[((size_t)bh*SS + s0 + row)*64 + c4];
            *(float4*)&Vp[row*ST + c4] = *(const float4*)&g_vp[((size_t)bh*64 + row)*SS + s0 + c4];
        }
        __syncthreads();

        // ---- S = Q K^T ----
        float sacc[8][4] = {};
        #pragma unroll
        for (int nb = 0; nb < 8; ++nb) {
            const float4* kr = (const float4*)&Kp[(8*nb + g)*ST + 16*q];
            float4 f0 = kr[0], f1 = kr[1], f2 = kr[2], f3 = kr[3];
            mma_tf32(sacc[nb], aq[0][0], aq[0][1], aq[0][2], aq[0][3], f0.x, f0.y);
            mma_tf32(sacc[nb], aq[1][0], aq[1][1], aq[1][2], aq[1][3], f0.z, f0.w);
            mma_tf32(sacc[nb], aq[2][0], aq[2][1], aq[2][2], aq[2][3], f1.x, f1.y);
            mma_tf32(sacc[nb], aq[3][0], aq[3][1], aq[3][2], aq[3][3], f1.z, f1.w);
            mma_tf32(sacc[nb], aq[4][0], aq[4][1], aq[4][2], aq[4][3], f2.x, f2.y);
            mma_tf32(sacc[nb], aq[5][0], aq[5][1], aq[5][2], aq[5][3], f2.z, f2.w);
            mma_tf32(sacc[nb], aq[6][0], aq[6][1], aq[6][2], aq[6][3], f3.x, f3.y);
            mma_tf32(sacc[nb], aq[7][0], aq[7][1], aq[7][2], aq[7][3], f3.z, f3.w);
        }

        // ---- P = exp(S * mask), store permuted+rounded; partial row sums ----
        float ps0 = 0.f, ps1 = 0.f;
        float2 m01 = __ldg((const float2*)&mrow0[s0 + 2*q]);
        float2 m23 = __ldg((const float2*)&mrow1[s0 + 2*q]);
        #pragma unroll
        for (int nb = 0; nb < 8; ++nb) {
            float2 n01 = m01, n23 = m23;
            if (nb < 7) {   // prefetch next
                m01 = __ldg((const float2*)&mrow0[s0 + 8*(nb + 1) + 2*q]);
                m23 = __ldg((const float2*)&mrow1[s0 + 8*(nb + 1) + 2*q]);
            }
            float p0 = frna(__expf(sacc[nb][0] * n01.x));
            float p1 = frna(__expf(sacc[nb][1] * n01.y));
            float p2 = frna(__expf(sacc[nb][2] * n23.x));
            float p3 = frna(__expf(sacc[nb][3] * n23.y));
            ps0 += p0 + p1; ps1 += p2 + p3;
            int pc = pc0 + 2*nb;
            Pp[g*ST + pc]            = p0;
            Pp[g*ST + pc + 16]       = p1;
            Pp[(g + 8)*ST + pc]      = p2;
            Pp[(g + 8)*ST + pc + 16] = p3;
        }
        ps0 += __shfl_xor_sync(0xffffffffu, ps0, 1);
        ps0 += __shfl_xor_sync(0xffffffffu, ps0, 2);
        ps1 += __shfl_xor_sync(0xffffffffu, ps1, 1);
        ps1 += __shfl_xor_sync(0xffffffffu, ps1, 2);
        lsum0 += ps0; lsum1 += ps1;
        __syncwarp();

        // ---- O += P V ----
        #pragma unroll
        for (int u = 0; u < 4; ++u) {
            float4 pa0 = *(const float4*)&Pp[g*ST       + 16*q + 4*u];
            float4 pa1 = *(const float4*)&Pp[(g + 8)*ST + 16*q + 4*u];
            #pragma unroll
            for (int nb = 0; nb < 8; ++nb) {
                float4 vb = *(const float4*)&Vp[(8*nb + g)*ST + 16*q + 4*u];
                mma_tf32(oacc[nb], pa0.x, pa1.x, pa0.y, pa1.y, vb.x, vb.y);
                mma_tf32(oacc[nb], pa0.z, pa1.z, pa0.w, pa1.w, vb.z, vb.w);
            }
        }
        __syncwarp();   // Pp reads done before next tile's epilogue rewrites
    }

    // normalize + write permuted+rounded to g_attp (b, s, h*64 + pk(c))
    float inv0 = 1.f / lsum0, inv1 = 1.f / lsum1;
    float* o0 = &g_attp[((size_t)b*SS + wr + g    )*EE + h*64];
    float* o1 = &g_attp[((size_t)b*SS + wr + g + 8)*EE + h*64];
    #pragma unroll
    for (int nb = 0; nb < 8; ++nb) {
        int pc = pc0 + 2*nb;
        o0[pc]      = frna(oacc[nb][0] * inv0);
        o0[pc + 16] = frna(oacc[nb][1] * inv0);
        o1[pc]      = frna(oacc[nb][2] * inv1);
        o1[pc + 16] = frna(oacc[nb][3] * inv1);
    }
}

// ---------------------------------------------------------------------------
// Kernel 3: output projection, 1x tf32 (all operands pre-rounded+permuted).
// out(4096x1024) = att @ Wo + bo.  CTA tile 128x64, K chunks of 64.
// ---------------------------------------------------------------------------
#define OUT_SMEM_FLOATS (128*ST + 64*ST)
#define OUT_SMEM_BYTES  (OUT_SMEM_FLOATS*4)

__global__ __launch_bounds__(256) void out_mma_kernel(
    const float* __restrict__ bo, float* __restrict__ out)
{
    extern __shared__ __align__(16) float smf[];
    float* As = smf;               // [m=128][pk(k)]
    float* Bs = smf + 128*ST;      // [n=64][pk(k)]

    int tid = threadIdx.x;
    int lane = tid & 31;
    int warp = tid >> 5;
    int g = lane >> 2, q = lane & 3;

    int e0 = blockIdx.x * 64;
    int r0 = blockIdx.y * 128;
    int wm = warp * 16;

    float oacc[8][4] = {};

    for (int kc = 0; kc < EE; kc += 64) {
        __syncthreads();
        for (int idx = tid; idx < 2048; idx += 256) {
            int row = idx >> 4, c4 = (idx & 15) * 4;
            *(float4*)&As[row*ST + c4] = *(const float4*)&g_attp[(size_t)(r0 + row)*EE + kc + c4];
        }
        for (int idx = tid; idx < 1024; idx += 256) {
            int row = idx >> 4, c4 = (idx & 15) * 4;
            *(float4*)&Bs[row*ST + c4] = *(const float4*)&g_wop[(size_t)(e0 + row)*EE + kc + c4];
        }
        __syncthreads();

        #pragma unroll
        for (int u = 0; u < 4; ++u) {
            float4 a0 = *(const float4*)&As[(wm + g    )*ST + 16*q + 4*u];
            float4 a1 = *(const float4*)&As[(wm + g + 8)*ST + 16*q + 4*u];
            #pragma unroll
            for (int nb = 0; nb < 8; ++nb) {
                float4 bb = *(const float4*)&Bs[(8*nb + g)*ST + 16*q + 4*u];
                mma_tf32(oacc[nb], a0.x, a1.x, a0.y, a1.y, bb.x, bb.y);
                mma_tf32(oacc[nb], a0.z, a1.z, a0.w, a1.w, bb.z, bb.w);
            }
        }
    }

    float* o0 = &out[(size_t)(r0 + wm + g    )*EE + e0];
    float* o1 = &out[(size_t)(r0 + wm + g + 8)*EE + e0];
    #pragma unroll
    for (int nb = 0; nb < 8; ++nb) {
        int c = nb*8 + 2*q;
        float bb0 = bo[e0 + c], bb1 = bo[e0 + c + 1];
        o0[c]     = oacc[nb][0] + bb0;
        o0[c + 1] = oacc[nb][1] + bb1;
        o1[c]     = oacc[nb][2] + bb0;
        o1[c + 1] = oacc[nb][3] + bb1;
    }
}

// ---------------------------------------------------------------------------
extern "C" void kernel_launch(void* const* d_in, const int* in_sizes, int n_in,
                              void* d_out, int out_size)
{
    const float* x    = (const float*)d_in[0];
    const float* mask = (const float*)d_in[1];
    const float* Wq   = (const float*)d_in[2];
    const float* bq   = (const float*)d_in[3];
    const float* Wk   = (const float*)d_in[4];
    const float* bk   = (const float*)d_in[5];
    const float* Wv   = (const float*)d_in[6];
    const float* bv   = (const float*)d_in[7];
    const float* Wo   = (const float*)d_in[8];
    const float* bo   = (const float*)d_in[9];
    float* out = (float*)d_out;

    cudaFuncSetAttribute(qkv_mma_kernel,  cudaFuncAttributeMaxDynamicSharedMemorySize, QKV_SMEM_BYTES);
    cudaFuncSetAttribute(attn_mma_kernel, cudaFuncAttributeMaxDynamicSharedMemorySize, ATTN_SMEM_BYTES);
    cudaFuncSetAttribute(out_mma_kernel,  cudaFuncAttributeMaxDynamicSharedMemorySize, OUT_SMEM_BYTES);

    wo_prep<<<dim3(EE/64, EE/32), 256>>>(Wo);
    qkv_mma_kernel<<<dim3(BH, SS/128), 256, QKV_SMEM_BYTES>>>(x, Wq, bq, Wk, bk, Wv, bv);
    attn_mma_kernel<<<dim3(BH, SS/128), 256, ATTN_SMEM_BYTES>>>(mask);
    out_mma_kernel<<<dim3(EE/64, (BB*SS)/128), 256, OUT_SMEM_BYTES>>>(bo, out);
}

// round 9
// speedup vs baseline: 1.7721x; 1.7721x over previous
#include <cuda_runtime.h>
#include <cuda_bf16.h>
#include <math.h>
#include <cstdint>

#define BB 2
#define SS 2048
#define EE 1024
#define HH 16
#define HD 64
#define BH (BB*HH)
#define SCALE 0.125f

// Scratch (16B-aligned: uint4 / cp.async sources)
static __device__ __align__(16) uint32_t g_qb[(size_t)BH*SS*32];
static __device__ __align__(16) uint32_t g_kb[(size_t)BH*SS*32];
static __device__ __align__(16) uint32_t g_vbh[(size_t)BH*64*(SS/2)];
static __device__ __align__(16) uint32_t g_vbl[(size_t)BH*64*(SS/2)];
static __device__ __align__(16) float    g_atto[(size_t)BB*SS*EE];

__device__ __forceinline__ uint32_t f2tf32(float x) {
    uint32_t r; asm("cvt.rna.tf32.f32 %0, %1;" : "=r"(r) : "f"(x)); return r;
}
__device__ __forceinline__ float frna(float x) { return __uint_as_float(f2tf32(x)); }
__device__ __forceinline__ void split_tf32(float x, float& hi, float& lo) {
    hi = frna(x); lo = frna(x - hi);
}
__device__ __forceinline__ uint32_t pack_bf16(float a, float b) {
    __nv_bfloat162 h = __floats2bfloat162_rn(a, b);
    return *reinterpret_cast<uint32_t*>(&h);
}
__device__ __forceinline__ void split_pack(float a, float b, uint32_t& hi, uint32_t& lo) {
    __nv_bfloat162 h = __floats2bfloat162_rn(a, b);
    lo = pack_bf16(a - __bfloat162float(h.x), b - __bfloat162float(h.y));
    hi = *reinterpret_cast<uint32_t*>(&h);
}
__device__ __forceinline__ uint32_t smem_u32(const void* p) {
    uint32_t a;
    asm("{ .reg .u64 t; cvta.to.shared.u64 t, %1; cvt.u32.u64 %0, t; }" : "=r"(a) : "l"(p));
    return a;
}
#define CPA16(d, s) asm volatile("cp.async.ca.shared.global [%0], [%1], 16;" :: "r"(d), "l"(s) : "memory")
#define CPC()       asm volatile("cp.async.commit_group;" ::: "memory")
#define CPW(n)      asm volatile("cp.async.wait_group %0;" :: "n"(n) : "memory")

__device__ __forceinline__ void mma_tf32(float c[4], float a0, float a1, float a2, float a3,
                                         float b0, float b1) {
    asm volatile("mma.sync.aligned.m16n8k8.row.col.f32.tf32.tf32.f32 "
        "{%0,%1,%2,%3}, {%4,%5,%6,%7}, {%8,%9}, {%0,%1,%2,%3};"
        : "+f"(c[0]), "+f"(c[1]), "+f"(c[2]), "+f"(c[3])
        : "r"(__float_as_uint(a0)), "r"(__float_as_uint(a1)),
          "r"(__float_as_uint(a2)), "r"(__float_as_uint(a3)),
          "r"(__float_as_uint(b0)), "r"(__float_as_uint(b1)));
}
__device__ __forceinline__ void mma_bf16(float c[4], uint32_t a0, uint32_t a1, uint32_t a2,
                                         uint32_t a3, uint32_t b0, uint32_t b1) {
    asm volatile("mma.sync.aligned.m16n8k16.row.col.f32.bf16.bf16.f32 "
        "{%0,%1,%2,%3}, {%4,%5,%6,%7}, {%8,%9}, {%0,%1,%2,%3};"
        : "+f"(c[0]), "+f"(c[1]), "+f"(c[2]), "+f"(c[3])
        : "r"(a0), "r"(a1), "r"(a2), "r"(a3), "r"(b0), "r"(b1));
}

// ---------------------------------------------------------------------------
// Kernel 1: QKV projection (tf32 mma) -> packed bf16 outputs.
// ---------------------------------------------------------------------------
#define QKV_SMEM_BYTES ((128*68 + 3*64*72)*4)

__global__ __launch_bounds__(256, 2) void qkv_kernel(
    const float* __restrict__ x,
    const float* __restrict__ Wq, const float* __restrict__ bq,
    const float* __restrict__ Wk, const float* __restrict__ bk,
    const float* __restrict__ Wv, const float* __restrict__ bv)
{
    extern __shared__ __align__(16) float smf[];
    float* At = smf;              // [128][k] stride 68
    float* Ws = smf + 128*68;     // 3 x [64][64] stride 72
    float* Vt = smf + 128*68;     // overlay after Ws done: [128 s][64 v] stride 65

    int tid = threadIdx.x, lane = tid & 31, warp = tid >> 5;
    int g = lane >> 2, q = lane & 3;
    int bh = blockIdx.x, b = bh >> 4, h = bh & 15;
    int s0 = blockIdx.y * 128, wm = warp * 16;

    for (int idx = tid; idx < 2048; idx += 256) {
        int row = idx >> 4, c4 = (idx & 15)*4;
        *(float4*)&At[row*68 + c4] = *(const float4*)&x[((size_t)b*SS + s0 + row)*EE + h*HD + c4];
    }
    const float* Wp[3] = {Wq, Wk, Wv};
    for (int w = 0; w < 3; ++w)
        for (int idx = tid; idx < 1024; idx += 256) {
            int row = idx >> 4, c4 = (idx & 15)*4;
            *(float4*)&Ws[w*64*72 + row*72 + c4] = *(const float4*)&Wp[w][(size_t)row*64 + c4];
        }
    __syncthreads();

    int r0g = s0 + wm + g, r1g = s0 + wm + g + 8;
    const float* bp[3] = {bq, bk, bv};

    for (int w = 0; w < 3; ++w) {
        float acc[8][4] = {};
        const float* B = &Ws[w*64*72];
        #pragma unroll
        for (int kk = 0; kk < 8; ++kk) {
            float a0 = frna(At[(wm + g)*68 + kk*8 + q]);
            float a1 = frna(At[(wm + g + 8)*68 + kk*8 + q]);
            float a2 = frna(At[(wm + g)*68 + kk*8 + q + 4]);
            float a3 = frna(At[(wm + g + 8)*68 + kk*8 + q + 4]);
            #pragma unroll
            for (int nb = 0; nb < 8; ++nb) {
                float b0 = frna(B[(kk*8 + q)*72 + nb*8 + g]);
                float b1 = frna(B[(kk*8 + q + 4)*72 + nb*8 + g]);
                mma_tf32(acc[nb], a0, a1, a2, a3, b0, b1);
            }
        }

        if (w == 0) {
            #pragma unroll
            for (int nb = 0; nb < 8; ++nb) {
                int c = nb*8 + 2*q;
                float b0 = bp[0][c], b1 = bp[0][c+1];
                g_qb[((size_t)bh*SS + r0g)*32 + q*8 + nb] = pack_bf16((acc[nb][0]+b0)*SCALE, (acc[nb][1]+b1)*SCALE);
                g_qb[((size_t)bh*SS + r1g)*32 + q*8 + nb] = pack_bf16((acc[nb][2]+b0)*SCALE, (acc[nb][3]+b1)*SCALE);
            }
        } else if (w == 1) {
            #pragma unroll
            for (int nb = 0; nb < 8; ++nb) {
                int c = nb*8 + 2*q;
                float b0 = bp[1][c], b1 = bp[1][c+1];
                g_kb[((size_t)bh*SS + r0g)*32 + q*8 + nb] = pack_bf16(acc[nb][0]+b0, acc[nb][1]+b1);
                g_kb[((size_t)bh*SS + r1g)*32 + q*8 + nb] = pack_bf16(acc[nb][2]+b0, acc[nb][3]+b1);
            }
        } else {
            __syncthreads();   // Ws reads done; Vt overlays
            int rl0 = wm + g, rl1 = wm + g + 8;
            #pragma unroll
            for (int nb = 0; nb < 8; ++nb) {
                int c = nb*8 + 2*q;
                float b0 = bp[2][c], b1 = bp[2][c+1];
                Vt[rl0*65 + c] = acc[nb][0]+b0; Vt[rl0*65 + c+1] = acc[nb][1]+b1;
                Vt[rl1*65 + c] = acc[nb][2]+b0; Vt[rl1*65 + c+1] = acc[nb][3]+b1;
            }
            __syncthreads();
            int v = tid & 63, idx2 = tid >> 6, tl = idx2 >> 1, half = idx2 & 1;
            uint32_t hi[16], lo[16];
            #pragma unroll
            for (int j = 0; j < 16; ++j) {
                int pos = half*16 + j;
                int qv = pos >> 3, kk = (pos & 7) >> 1, hh = pos & 1;
                int sl = tl*64 + 2*(8*kk + 4*hh + qv);
                split_pack(Vt[sl*65 + v], Vt[(sl+1)*65 + v], hi[j], lo[j]);
            }
            size_t ob = ((size_t)bh*64 + v)*(SS/2) + (s0 >> 1) + tl*32 + half*16;
            #pragma unroll
            for (int u = 0; u < 4; ++u) {
                *(uint4*)&g_vbh[ob + 4*u] = make_uint4(hi[4*u], hi[4*u+1], hi[4*u+2], hi[4*u+3]);
                *(uint4*)&g_vbl[ob + 4*u] = make_uint4(lo[4*u], lo[4*u+1], lo[4*u+2], lo[4*u+3]);
            }
        }
    }
}

// ---------------------------------------------------------------------------
// Kernel 2: attention, bf16 mma, P-in-register, cp.async 3-stage pipeline.
// Smem tiles: stride 32 u32/row + XOR-16B-chunk swizzle (chunk ^= row&7).
// ---------------------------------------------------------------------------
#define SSTG (3*64*32)                  // u32 per stage (K,Vh,Vl) = 6144
#define ATTN_SMEM_BYTES (3*SSTG*4)      // 73728

__global__ __launch_bounds__(256, 2) void attn_kernel(const float* __restrict__ mask)
{
    extern __shared__ __align__(16) uint32_t smu[];
    uint32_t smb = smem_u32(smu);

    int tid = threadIdx.x, lane = tid & 31, warp = tid >> 5;
    int g = lane >> 2, q = lane & 3;
    int bh = blockIdx.x, b = bh >> 4, h = bh & 15;
    int q0 = blockIdx.y * 128, wr = q0 + warp*16;

    int r8 = tid >> 3, seg = tid & 7;
    const char* srcK = (const char*)g_kb  + ((size_t)bh*SS)*128;
    const char* srcH = (const char*)g_vbh + ((size_t)bh*64)*(SS/2)*4;
    const char* srcL = (const char*)g_vbl + ((size_t)bh*64)*(SS/2)*4;

    #pragma unroll
    for (int pf = 0; pf < 2; ++pf) {
        int s0 = pf*64;
        uint32_t base = smb + (pf % 3)*SSTG*4;
        #pragma unroll
        for (int t = 0; t < 2; ++t) {
            int row = r8 + 32*t;
            int sc = (seg ^ (row & 7))*16;               // swizzled source chunk
            uint32_t doff = row*128 + seg*16;
            CPA16(base + doff,            srcK + (size_t)(s0+row)*128 + sc);
            CPA16(base + 8192 + doff,     srcH + ((size_t)row*(SS/2) + (s0>>1))*4 + sc);
            CPA16(base + 16384 + doff,    srcL + ((size_t)row*(SS/2) + (s0>>1))*4 + sc);
        }
        CPC();
    }

    // Q fragments
    uint32_t qa[8], qg[8];
    {
        const uint4* p0 = (const uint4*)&g_qb[((size_t)bh*SS + wr + g)*32 + q*8];
        const uint4* p1 = (const uint4*)&g_qb[((size_t)bh*SS + wr + g + 8)*32 + q*8];
        uint4 u0 = p0[0], u1 = p0[1], v0 = p1[0], v1 = p1[1];
        qa[0]=u0.x; qa[1]=u0.y; qa[2]=u0.z; qa[3]=u0.w; qa[4]=u1.x; qa[5]=u1.y; qa[6]=u1.z; qa[7]=u1.w;
        qg[0]=v0.x; qg[1]=v0.y; qg[2]=v0.z; qg[3]=v0.w; qg[4]=v1.x; qg[5]=v1.y; qg[6]=v1.z; qg[7]=v1.w;
    }

    float oacc[8][4] = {};
    float lsum0 = 0.f, lsum1 = 0.f;
    const float* mrow0 = &mask[(size_t)(wr + g)*SS];
    const float* mrow1 = &mask[(size_t)(wr + g + 8)*SS];
    int u0c = ((2*q) ^ g)*4;        // swizzled u32 offset of data chunk 2q
    int u1c = ((2*q + 1) ^ g)*4;    // data chunk 2q+1

    for (int jt = 0; jt < 32; ++jt) {
        if (jt < 31) { CPW(1); } else { CPW(0); }
        __syncthreads();
        if (jt + 2 < 32) {
            int s0n = (jt+2)*64;
            uint32_t base = smb + ((jt+2) % 3)*SSTG*4;
            #pragma unroll
            for (int t = 0; t < 2; ++t) {
                int row = r8 + 32*t;
                int sc = (seg ^ (row & 7))*16;
                uint32_t doff = row*128 + seg*16;
                CPA16(base + doff,         srcK + (size_t)(s0n+row)*128 + sc);
                CPA16(base + 8192 + doff,  srcH + ((size_t)row*(SS/2) + (s0n>>1))*4 + sc);
                CPA16(base + 16384 + doff, srcL + ((size_t)row*(SS/2) + (s0n>>1))*4 + sc);
            }
            CPC();
        }

        const uint32_t* Kb = smu + (jt % 3)*SSTG;
        const uint32_t* Vh = Kb + 2048;
        const uint32_t* Vl = Kb + 4096;
        int s0 = jt*64;

        // S = Q K^T
        float sacc[8][4] = {};
        #pragma unroll
        for (int nb = 0; nb < 8; ++nb) {
            int rb = (8*nb + g)*32;
            uint4 k0 = *(const uint4*)&Kb[rb + u0c];
            uint4 k1 = *(const uint4*)&Kb[rb + u1c];
            mma_bf16(sacc[nb], qa[0], qg[0], qa[1], qg[1], k0.x, k0.y);
            mma_bf16(sacc[nb], qa[2], qg[2], qa[3], qg[3], k0.z, k0.w);
            mma_bf16(sacc[nb], qa[4], qg[4], qa[5], qg[5], k1.x, k1.y);
            mma_bf16(sacc[nb], qa[6], qg[6], qa[7], qg[7], k1.z, k1.w);
        }

        // P = exp(S*mask) packed into A-fragments (hi/lo)
        uint32_t ph[8], pg[8], pl[8], pm[8];
        float ps0 = 0.f, ps1 = 0.f;
        #pragma unroll
        for (int nb = 0; nb < 8; ++nb) {
            float2 m0 = __ldg((const float2*)&mrow0[s0 + 8*nb + 2*q]);
            float2 m1 = __ldg((const float2*)&mrow1[s0 + 8*nb + 2*q]);
            float p0 = __expf(sacc[nb][0]*m0.x);
            float p1 = __expf(sacc[nb][1]*m0.y);
            float p2 = __expf(sacc[nb][2]*m1.x);
            float p3 = __expf(sacc[nb][3]*m1.y);
            ps0 += p0 + p1; ps1 += p2 + p3;
            split_pack(p0, p1, ph[nb], pl[nb]);
            split_pack(p2, p3, pg[nb], pm[nb]);
        }
        ps0 += __shfl_xor_sync(0xffffffffu, ps0, 1);
        ps0 += __shfl_xor_sync(0xffffffffu, ps0, 2);
        ps1 += __shfl_xor_sync(0xffffffffu, ps1, 1);
        ps1 += __shfl_xor_sync(0xffffffffu, ps1, 2);
        lsum0 += ps0; lsum1 += ps1;

        // O += P V  (Ph*Vh + Pl*Vh + Ph*Vl)
        #pragma unroll
        for (int nb = 0; nb < 8; ++nb) {
            int rb = (8*nb + g)*32;
            uint4 h0 = *(const uint4*)&Vh[rb + u0c];
            uint4 h1 = *(const uint4*)&Vh[rb + u1c];
            uint4 l0 = *(const uint4*)&Vl[rb + u0c];
            uint4 l1 = *(const uint4*)&Vl[rb + u1c];
            mma_bf16(oacc[nb], ph[0], pg[0], ph[1], pg[1], h0.x, h0.y);
            mma_bf16(oacc[nb], pl[0], pm[0], pl[1], pm[1], h0.x, h0.y);
            mma_bf16(oacc[nb], ph[0], pg[0], ph[1], pg[1], l0.x, l0.y);
            mma_bf16(oacc[nb], ph[2], pg[2], ph[3], pg[3], h0.z, h0.w);
            mma_bf16(oacc[nb], pl[2], pm[2], pl[3], pm[3], h0.z, h0.w);
            mma_bf16(oacc[nb], ph[2], pg[2], ph[3], pg[3], l0.z, l0.w);
            mma_bf16(oacc[nb], ph[4], pg[4], ph[5], pg[5], h1.x, h1.y);
            mma_bf16(oacc[nb], pl[4], pm[4], pl[5], pm[5], h1.x, h1.y);
            mma_bf16(oacc[nb], ph[4], pg[4], ph[5], pg[5], l1.x, l1.y);
            mma_bf16(oacc[nb], ph[6], pg[6], ph[7], pg[7], h1.z, h1.w);
            mma_bf16(oacc[nb], pl[6], pm[6], pl[7], pm[7], h1.z, h1.w);
            mma_bf16(oacc[nb], ph[6], pg[6], ph[7], pg[7], l1.z, l1.w);
        }
    }

    float inv0 = 1.f/lsum0, inv1 = 1.f/lsum1;
    float* o0 = &g_atto[((size_t)b*SS + wr + g)*EE + h*64];
    float* o1 = &g_atto[((size_t)b*SS + wr + g + 8)*EE + h*64];
    #pragma unroll
    for (int nb = 0; nb < 8; ++nb) {
        int c = nb*8 + 2*q;
        o0[c] = oacc[nb][0]*inv0; o0[c+1] = oacc[nb][1]*inv0;
        o1[c] = oacc[nb][2]*inv1; o1[c+1] = oacc[nb][3]*inv1;
    }
}

// ---------------------------------------------------------------------------
// Kernel 3: output projection, tf32 (A 2x split, B rna), cp.async 2-stage.
// ---------------------------------------------------------------------------
#define OSTG (128*68 + 64*72)
#define OUT_SMEM_BYTES (2*OSTG*4)

__global__ __launch_bounds__(256, 2) void out_kernel(
    const float* __restrict__ Wo, const float* __restrict__ bo, float* __restrict__ out)
{
    extern __shared__ __align__(16) float smo[];
    uint32_t smb = smem_u32(smo);

    int tid = threadIdx.x, lane = tid & 31, warp = tid >> 5;
    int g = lane >> 2, q = lane & 3;
    int e0 = blockIdx.x*64, r0 = blockIdx.y*128, wm = warp*16;

    int r16 = tid >> 4, seg = tid & 15;
    const char* srcA = (const char*)g_atto + (size_t)r0*EE*4;
    const char* srcB = (const char*)Wo + (size_t)e0*4;

    {
        uint32_t base = smb;
        #pragma unroll
        for (int t = 0; t < 8; ++t) {
            int row = r16 + 16*t;
            CPA16(base + (row*68 + seg*4)*4, srcA + ((size_t)row*EE)*4 + seg*16);
        }
        #pragma unroll
        for (int t = 0; t < 4; ++t) {
            int row = r16 + 16*t;
            CPA16(base + (128*68 + row*72 + seg*4)*4, srcB + ((size_t)row*EE)*4 + seg*16);
        }
        CPC();
    }

    float oacc[8][4] = {};

    for (int j = 0; j < 16; ++j) {
        CPW(0);
        __syncthreads();
        if (j + 1 < 16) {
            int kc = (j+1)*64;
            uint32_t base = smb + ((j+1) & 1)*OSTG*4;
            #pragma unroll
            for (int t = 0; t < 8; ++t) {
                int row = r16 + 16*t;
                CPA16(base + (row*68 + seg*4)*4, srcA + ((size_t)row*EE + kc)*4 + seg*16);
            }
            #pragma unroll
            for (int t = 0; t < 4; ++t) {
                int row = r16 + 16*t;
                CPA16(base + (128*68 + row*72 + seg*4)*4, srcB + ((size_t)(kc+row)*EE)*4 + seg*16);
            }
            CPC();
        }

        const float* As = smo + (j & 1)*OSTG;
        const float* Bs = As + 128*68;

        #pragma unroll
        for (int kk = 0; kk < 8; ++kk) {
            float ah[4], al[4];
            split_tf32(As[(wm + g)*68 + kk*8 + q],       ah[0], al[0]);
            split_tf32(As[(wm + g + 8)*68 + kk*8 + q],   ah[1], al[1]);
            split_tf32(As[(wm + g)*68 + kk*8 + q + 4],   ah[2], al[2]);
            split_tf32(As[(wm + g + 8)*68 + kk*8 + q+4], ah[3], al[3]);
            #pragma unroll
            for (int nb = 0; nb < 8; ++nb) {
                float b0 = frna(Bs[(kk*8 + q)*72 + nb*8 + g]);
                float b1 = frna(Bs[(kk*8 + q + 4)*72 + nb*8 + g]);
                mma_tf32(oacc[nb], ah[0], ah[1], ah[2], ah[3], b0, b1);
                mma_tf32(oacc[nb], al[0], al[1], al[2], al[3], b0, b1);
            }
        }
    }

    float* o0 = &out[(size_t)(r0 + wm + g)*EE + e0];
    float* o1 = &out[(size_t)(r0 + wm + g + 8)*EE + e0];
    #pragma unroll
    for (int nb = 0; nb < 8; ++nb) {
        int c = nb*8 + 2*q;
        float b0 = bo[e0 + c], b1 = bo[e0 + c + 1];
        o0[c] = oacc[nb][0] + b0; o0[c+1] = oacc[nb][1] + b1;
        o1[c] = oacc[nb][2] + b0; o1[c+1] = oacc[nb][3] + b1;
    }
}

// ---------------------------------------------------------------------------
extern "C" void kernel_launch(void* const* d_in, const int* in_sizes, int n_in,
                              void* d_out, int out_size)
{
    const float* x    = (const float*)d_in[0];
    const float* mask = (const float*)d_in[1];
    const float* Wq   = (const float*)d_in[2];
    const float* bq   = (const float*)d_in[3];
    const float* Wk   = (const float*)d_in[4];
    const float* bk   = (const float*)d_in[5];
    const float* Wv   = (const float*)d_in[6];
    const float* bv   = (const float*)d_in[7];
    const float* Wo   = (const float*)d_in[8];
    const float* bo   = (const float*)d_in[9];
    float* out = (float*)d_out;

    cudaFuncSetAttribute(qkv_kernel,  cudaFuncAttributeMaxDynamicSharedMemorySize, QKV_SMEM_BYTES);
    cudaFuncSetAttribute(attn_kernel, cudaFuncAttributeMaxDynamicSharedMemorySize, ATTN_SMEM_BYTES);
    cudaFuncSetAttribute(out_kernel,  cudaFuncAttributeMaxDynamicSharedMemorySize, OUT_SMEM_BYTES);

    qkv_kernel<<<dim3(BH, SS/128), 256, QKV_SMEM_BYTES>>>(x, Wq, bq, Wk, bk, Wv, bv);
    attn_kernel<<<dim3(BH, SS/128), 256, ATTN_SMEM_BYTES>>>(mask);
    out_kernel<<<dim3(EE/64, (BB*SS)/128), 256, OUT_SMEM_BYTES>>>(Wo, bo, out);
}

// round 10
// speedup vs baseline: 1.9325x; 1.0905x over previous
#include <cuda_runtime.h>
#include <cuda_bf16.h>
#include <math.h>
#include <cstdint>

#define BB 2
#define SS 2048
#define EE 1024
#define HH 16
#define HD 64
#define BH (BB*HH)
#define SCALE 0.125f

// Scratch (16B-aligned: uint4 / cp.async sources)
static __device__ __align__(16) uint32_t g_qb[(size_t)BH*SS*32];
static __device__ __align__(16) uint32_t g_kb[(size_t)BH*SS*32];
static __device__ __align__(16) uint32_t g_vbh[(size_t)BH*64*(SS/2)];
static __device__ __align__(16) uint32_t g_vbl[(size_t)BH*64*(SS/2)];
static __device__ __align__(16) uint32_t g_ath[(size_t)BB*SS*(EE/2)];  // att hi pairs, A-frag layout
static __device__ __align__(16) uint32_t g_atl[(size_t)BB*SS*(EE/2)];  // att lo
static __device__ __align__(16) uint32_t g_woh[(size_t)EE*(EE/2)];     // Wo^T hi pairs, B-frag layout
static __device__ __align__(16) uint32_t g_wol[(size_t)EE*(EE/2)];     // Wo^T lo

__device__ __forceinline__ uint32_t f2tf32(float x) {
    uint32_t r; asm("cvt.rna.tf32.f32 %0, %1;" : "=r"(r) : "f"(x)); return r;
}
__device__ __forceinline__ float frna(float x) { return __uint_as_float(f2tf32(x)); }
__device__ __forceinline__ uint32_t pack_bf16(float a, float b) {
    __nv_bfloat162 h = __floats2bfloat162_rn(a, b);
    return *reinterpret_cast<uint32_t*>(&h);
}
__device__ __forceinline__ void split_pack(float a, float b, uint32_t& hi, uint32_t& lo) {
    __nv_bfloat162 h = __floats2bfloat162_rn(a, b);
    lo = pack_bf16(a - __bfloat162float(h.x), b - __bfloat162float(h.y));
    hi = *reinterpret_cast<uint32_t*>(&h);
}
__device__ __forceinline__ uint32_t smem_u32(const void* p) {
    uint32_t a;
    asm("{ .reg .u64 t; cvta.to.shared.u64 t, %1; cvt.u32.u64 %0, t; }" : "=r"(a) : "l"(p));
    return a;
}
#define CPA16(d, s) asm volatile("cp.async.ca.shared.global [%0], [%1], 16;" :: "r"(d), "l"(s) : "memory")
#define CPC()       asm volatile("cp.async.commit_group;" ::: "memory")
#define CPW(n)      asm volatile("cp.async.wait_group %0;" :: "n"(n) : "memory")

__device__ __forceinline__ void mma_tf32(float c[4], float a0, float a1, float a2, float a3,
                                         float b0, float b1) {
    asm volatile("mma.sync.aligned.m16n8k8.row.col.f32.tf32.tf32.f32 "
        "{%0,%1,%2,%3}, {%4,%5,%6,%7}, {%8,%9}, {%0,%1,%2,%3};"
        : "+f"(c[0]), "+f"(c[1]), "+f"(c[2]), "+f"(c[3])
        : "r"(__float_as_uint(a0)), "r"(__float_as_uint(a1)),
          "r"(__float_as_uint(a2)), "r"(__float_as_uint(a3)),
          "r"(__float_as_uint(b0)), "r"(__float_as_uint(b1)));
}
__device__ __forceinline__ void mma_bf16(float c[4], uint32_t a0, uint32_t a1, uint32_t a2,
                                         uint32_t a3, uint32_t b0, uint32_t b1) {
    asm volatile("mma.sync.aligned.m16n8k16.row.col.f32.bf16.bf16.f32 "
        "{%0,%1,%2,%3}, {%4,%5,%6,%7}, {%8,%9}, {%0,%1,%2,%3};"
        : "+f"(c[0]), "+f"(c[1]), "+f"(c[2]), "+f"(c[3])
        : "r"(a0), "r"(a1), "r"(a2), "r"(a3), "r"(b0), "r"(b1));
}

// ---------------------------------------------------------------------------
// Kernel 0: pack Wo into hi/lo bf16x2 pairs, B-fragment layout.
// g_woh[n][chunk*32 + (pr&3)*8 + (pr>>2)] = hi(Wo[chunk*64+2*pr][n], ...+1)
// ---------------------------------------------------------------------------
__global__ __launch_bounds__(256) void wo_pack(const float* __restrict__ Wo)
{
    __shared__ float t[64][65];
    int k0 = blockIdx.x*64, n0 = blockIdx.y*64;
    int tid = threadIdx.x;

    for (int idx = tid; idx < 4096; idx += 256) {
        int ki = idx >> 6, n = idx & 63;
        t[ki][n] = Wo[(size_t)(k0 + ki)*EE + n0 + n];
    }
    __syncthreads();

    int nl = tid >> 2, qq = tid & 3;
    uint32_t hi[8], lo[8];
    #pragma unroll
    for (int j = 0; j < 8; ++j) {
        int pr = 4*j + qq;                       // logical pair, stored at pos qq*8+j
        split_pack(t[2*pr][nl], t[2*pr + 1][nl], hi[j], lo[j]);
    }
    size_t ob = (size_t)(n0 + nl)*(EE/2) + (k0 >> 6)*32 + qq*8;
    *(uint4*)&g_woh[ob]     = make_uint4(hi[0], hi[1], hi[2], hi[3]);
    *(uint4*)&g_woh[ob + 4] = make_uint4(hi[4], hi[5], hi[6], hi[7]);
    *(uint4*)&g_wol[ob]     = make_uint4(lo[0], lo[1], lo[2], lo[3]);
    *(uint4*)&g_wol[ob + 4] = make_uint4(lo[4], lo[5], lo[6], lo[7]);
}

// ---------------------------------------------------------------------------
// Kernel 1: QKV projection (tf32 mma) -> packed bf16 outputs.
// ---------------------------------------------------------------------------
#define QKV_SMEM_BYTES ((128*68 + 3*64*72)*4)

__global__ __launch_bounds__(256, 2) void qkv_kernel(
    const float* __restrict__ x,
    const float* __restrict__ Wq, const float* __restrict__ bq,
    const float* __restrict__ Wk, const float* __restrict__ bk,
    const float* __restrict__ Wv, const float* __restrict__ bv)
{
    extern __shared__ __align__(16) float smf[];
    float* At = smf;              // [128][k] stride 68
    float* Ws = smf + 128*68;     // 3 x [64][64] stride 72
    float* Vt = smf + 128*68;     // overlay after Ws done: [128 s][64 v] stride 65

    int tid = threadIdx.x, lane = tid & 31, warp = tid >> 5;
    int g = lane >> 2, q = lane & 3;
    int bh = blockIdx.x, b = bh >> 4, h = bh & 15;
    int s0 = blockIdx.y * 128, wm = warp * 16;
    (void)b; (void)h;

    for (int idx = tid; idx < 2048; idx += 256) {
        int row = idx >> 4, c4 = (idx & 15)*4;
        *(float4*)&At[row*68 + c4] = *(const float4*)&x[((size_t)b*SS + s0 + row)*EE + h*HD + c4];
    }
    const float* Wp[3] = {Wq, Wk, Wv};
    for (int w = 0; w < 3; ++w)
        for (int idx = tid; idx < 1024; idx += 256) {
            int row = idx >> 4, c4 = (idx & 15)*4;
            *(float4*)&Ws[w*64*72 + row*72 + c4] = *(const float4*)&Wp[w][(size_t)row*64 + c4];
        }
    __syncthreads();

    int r0g = s0 + wm + g, r1g = s0 + wm + g + 8;
    const float* bp[3] = {bq, bk, bv};

    for (int w = 0; w < 3; ++w) {
        float acc[8][4] = {};
        const float* B = &Ws[w*64*72];
        #pragma unroll
        for (int kk = 0; kk < 8; ++kk) {
            float a0 = frna(At[(wm + g)*68 + kk*8 + q]);
            float a1 = frna(At[(wm + g + 8)*68 + kk*8 + q]);
            float a2 = frna(At[(wm + g)*68 + kk*8 + q + 4]);
            float a3 = frna(At[(wm + g + 8)*68 + kk*8 + q + 4]);
            #pragma unroll
            for (int nb = 0; nb < 8; ++nb) {
                float b0 = frna(B[(kk*8 + q)*72 + nb*8 + g]);
                float b1 = frna(B[(kk*8 + q + 4)*72 + nb*8 + g]);
                mma_tf32(acc[nb], a0, a1, a2, a3, b0, b1);
            }
        }

        if (w == 0) {
            #pragma unroll
            for (int nb = 0; nb < 8; ++nb) {
                int c = nb*8 + 2*q;
                float b0 = bp[0][c], b1 = bp[0][c+1];
                g_qb[((size_t)bh*SS + r0g)*32 + q*8 + nb] = pack_bf16((acc[nb][0]+b0)*SCALE, (acc[nb][1]+b1)*SCALE);
                g_qb[((size_t)bh*SS + r1g)*32 + q*8 + nb] = pack_bf16((acc[nb][2]+b0)*SCALE, (acc[nb][3]+b1)*SCALE);
            }
        } else if (w == 1) {
            #pragma unroll
            for (int nb = 0; nb < 8; ++nb) {
                int c = nb*8 + 2*q;
                float b0 = bp[1][c], b1 = bp[1][c+1];
                g_kb[((size_t)bh*SS + r0g)*32 + q*8 + nb] = pack_bf16(acc[nb][0]+b0, acc[nb][1]+b1);
                g_kb[((size_t)bh*SS + r1g)*32 + q*8 + nb] = pack_bf16(acc[nb][2]+b0, acc[nb][3]+b1);
            }
        } else {
            __syncthreads();   // Ws reads done; Vt overlays
            int rl0 = wm + g, rl1 = wm + g + 8;
            #pragma unroll
            for (int nb = 0; nb < 8; ++nb) {
                int c = nb*8 + 2*q;
                float b0 = bp[2][c], b1 = bp[2][c+1];
                Vt[rl0*65 + c] = acc[nb][0]+b0; Vt[rl0*65 + c+1] = acc[nb][1]+b1;
                Vt[rl1*65 + c] = acc[nb][2]+b0; Vt[rl1*65 + c+1] = acc[nb][3]+b1;
            }
            __syncthreads();
            int v = tid & 63, idx2 = tid >> 6, tl = idx2 >> 1, half = idx2 & 1;
            uint32_t hi[16], lo[16];
            #pragma unroll
            for (int j = 0; j < 16; ++j) {
                int pos = half*16 + j;
                int qv = pos >> 3, kk = (pos & 7) >> 1, hh = pos & 1;
                int sl = tl*64 + 2*(8*kk + 4*hh + qv);
                split_pack(Vt[sl*65 + v], Vt[(sl+1)*65 + v], hi[j], lo[j]);
            }
            size_t ob = ((size_t)bh*64 + v)*(SS/2) + (s0 >> 1) + tl*32 + half*16;
            #pragma unroll
            for (int u = 0; u < 4; ++u) {
                *(uint4*)&g_vbh[ob + 4*u] = make_uint4(hi[4*u], hi[4*u+1], hi[4*u+2], hi[4*u+3]);
                *(uint4*)&g_vbl[ob + 4*u] = make_uint4(lo[4*u], lo[4*u+1], lo[4*u+2], lo[4*u+3]);
            }
        }
    }
}

// ---------------------------------------------------------------------------
// Kernel 2: attention, bf16 mma, P-in-register, cp.async 3-stage pipeline.
// Epilogue writes O as split hi/lo bf16x2 pairs in A-fragment layout.
// ---------------------------------------------------------------------------
#define SSTG (3*64*32)
#define ATTN_SMEM_BYTES (3*SSTG*4)

__global__ __launch_bounds__(256, 2) void attn_kernel(const float* __restrict__ mask)
{
    extern __shared__ __align__(16) uint32_t smu[];
    uint32_t smb = smem_u32(smu);

    int tid = threadIdx.x, lane = tid & 31, warp = tid >> 5;
    int g = lane >> 2, q = lane & 3;
    int bh = blockIdx.x, b = bh >> 4, h = bh & 15;
    int q0 = blockIdx.y * 128, wr = q0 + warp*16;

    int r8 = tid >> 3, seg = tid & 7;
    const char* srcK = (const char*)g_kb  + ((size_t)bh*SS)*128;
    const char* srcH = (const char*)g_vbh + ((size_t)bh*64)*(SS/2)*4;
    const char* srcL = (const char*)g_vbl + ((size_t)bh*64)*(SS/2)*4;

    #pragma unroll
    for (int pf = 0; pf < 2; ++pf) {
        int s0 = pf*64;
        uint32_t base = smb + (pf % 3)*SSTG*4;
        #pragma unroll
        for (int t = 0; t < 2; ++t) {
            int row = r8 + 32*t;
            int sc = (seg ^ (row & 7))*16;
            uint32_t doff = row*128 + seg*16;
            CPA16(base + doff,            srcK + (size_t)(s0+row)*128 + sc);
            CPA16(base + 8192 + doff,     srcH + ((size_t)row*(SS/2) + (s0>>1))*4 + sc);
            CPA16(base + 16384 + doff,    srcL + ((size_t)row*(SS/2) + (s0>>1))*4 + sc);
        }
        CPC();
    }

    uint32_t qa[8], qg[8];
    {
        const uint4* p0 = (const uint4*)&g_qb[((size_t)bh*SS + wr + g)*32 + q*8];
        const uint4* p1 = (const uint4*)&g_qb[((size_t)bh*SS + wr + g + 8)*32 + q*8];
        uint4 u0 = p0[0], u1 = p0[1], v0 = p1[0], v1 = p1[1];
        qa[0]=u0.x; qa[1]=u0.y; qa[2]=u0.z; qa[3]=u0.w; qa[4]=u1.x; qa[5]=u1.y; qa[6]=u1.z; qa[7]=u1.w;
        qg[0]=v0.x; qg[1]=v0.y; qg[2]=v0.z; qg[3]=v0.w; qg[4]=v1.x; qg[5]=v1.y; qg[6]=v1.z; qg[7]=v1.w;
    }

    float oacc[8][4] = {};
    float lsum0 = 0.f, lsum1 = 0.f;
    const float* mrow0 = &mask[(size_t)(wr + g)*SS];
    const float* mrow1 = &mask[(size_t)(wr + g + 8)*SS];
    int u0c = ((2*q) ^ g)*4;
    int u1c = ((2*q + 1) ^ g)*4;

    for (int jt = 0; jt < 32; ++jt) {
        if (jt < 31) { CPW(1); } else { CPW(0); }
        __syncthreads();
        if (jt + 2 < 32) {
            int s0n = (jt+2)*64;
            uint32_t base = smb + ((jt+2) % 3)*SSTG*4;
            #pragma unroll
            for (int t = 0; t < 2; ++t) {
                int row = r8 + 32*t;
                int sc = (seg ^ (row & 7))*16;
                uint32_t doff = row*128 + seg*16;
                CPA16(base + doff,         srcK + (size_t)(s0n+row)*128 + sc);
                CPA16(base + 8192 + doff,  srcH + ((size_t)row*(SS/2) + (s0n>>1))*4 + sc);
                CPA16(base + 16384 + doff, srcL + ((size_t)row*(SS/2) + (s0n>>1))*4 + sc);
            }
            CPC();
        }

        const uint32_t* Kb = smu + (jt % 3)*SSTG;
        const uint32_t* Vh = Kb + 2048;
        const uint32_t* Vl = Kb + 4096;
        int s0 = jt*64;

        float sacc[8][4] = {};
        #pragma unroll
        for (int nb = 0; nb < 8; ++nb) {
            int rb = (8*nb + g)*32;
            uint4 k0 = *(const uint4*)&Kb[rb + u0c];
            uint4 k1 = *(const uint4*)&Kb[rb + u1c];
            mma_bf16(sacc[nb], qa[0], qg[0], qa[1], qg[1], k0.x, k0.y);
            mma_bf16(sacc[nb], qa[2], qg[2], qa[3], qg[3], k0.z, k0.w);
            mma_bf16(sacc[nb], qa[4], qg[4], qa[5], qg[5], k1.x, k1.y);
            mma_bf16(sacc[nb], qa[6], qg[6], qa[7], qg[7], k1.z, k1.w);
        }

        uint32_t ph[8], pg[8], pl[8], pm[8];
        float ps0 = 0.f, ps1 = 0.f;
        #pragma unroll
        for (int nb = 0; nb < 8; ++nb) {
            float2 m0 = __ldg((const float2*)&mrow0[s0 + 8*nb + 2*q]);
            float2 m1 = __ldg((const float2*)&mrow1[s0 + 8*nb + 2*q]);
            float p0 = __expf(sacc[nb][0]*m0.x);
            float p1 = __expf(sacc[nb][1]*m0.y);
            float p2 = __expf(sacc[nb][2]*m1.x);
            float p3 = __expf(sacc[nb][3]*m1.y);
            ps0 += p0 + p1; ps1 += p2 + p3;
            split_pack(p0, p1, ph[nb], pl[nb]);
            split_pack(p2, p3, pg[nb], pm[nb]);
        }
        ps0 += __shfl_xor_sync(0xffffffffu, ps0, 1);
        ps0 += __shfl_xor_sync(0xffffffffu, ps0, 2);
        ps1 += __shfl_xor_sync(0xffffffffu, ps1, 1);
        ps1 += __shfl_xor_sync(0xffffffffu, ps1, 2);
        lsum0 += ps0; lsum1 += ps1;

        #pragma unroll
        for (int nb = 0; nb < 8; ++nb) {
            int rb = (8*nb + g)*32;
            uint4 h0 = *(const uint4*)&Vh[rb + u0c];
            uint4 h1 = *(const uint4*)&Vh[rb + u1c];
            uint4 l0 = *(const uint4*)&Vl[rb + u0c];
            uint4 l1 = *(const uint4*)&Vl[rb + u1c];
            mma_bf16(oacc[nb], ph[0], pg[0], ph[1], pg[1], h0.x, h0.y);
            mma_bf16(oacc[nb], pl[0], pm[0], pl[1], pm[1], h0.x, h0.y);
            mma_bf16(oacc[nb], ph[0], pg[0], ph[1], pg[1], l0.x, l0.y);
            mma_bf16(oacc[nb], ph[2], pg[2], ph[3], pg[3], h0.z, h0.w);
            mma_bf16(oacc[nb], pl[2], pm[2], pl[3], pm[3], h0.z, h0.w);
            mma_bf16(oacc[nb], ph[2], pg[2], ph[3], pg[3], l0.z, l0.w);
            mma_bf16(oacc[nb], ph[4], pg[4], ph[5], pg[5], h1.x, h1.y);
            mma_bf16(oacc[nb], pl[4], pm[4], pl[5], pm[5], h1.x, h1.y);
            mma_bf16(oacc[nb], ph[4], pg[4], ph[5], pg[5], l1.x, l1.y);
            mma_bf16(oacc[nb], ph[6], pg[6], ph[7], pg[7], h1.z, h1.w);
            mma_bf16(oacc[nb], pl[6], pm[6], pl[7], pm[7], h1.z, h1.w);
            mma_bf16(oacc[nb], ph[6], pg[6], ph[7], pg[7], l1.z, l1.w);
        }
    }

    // epilogue: normalize, split-pack, write in A-fragment layout (pos q*8+nb)
    float inv0 = 1.f/lsum0, inv1 = 1.f/lsum1;
    size_t base0 = ((size_t)b*SS + wr + g)*(EE/2) + h*32;
    size_t base1 = ((size_t)b*SS + wr + g + 8)*(EE/2) + h*32;
    #pragma unroll
    for (int nb = 0; nb < 8; ++nb) {
        int pos = q*8 + nb;
        uint32_t hi, lo;
        split_pack(oacc[nb][0]*inv0, oacc[nb][1]*inv0, hi, lo);
        g_ath[base0 + pos] = hi; g_atl[base0 + pos] = lo;
        split_pack(oacc[nb][2]*inv1, oacc[nb][3]*inv1, hi, lo);
        g_ath[base1 + pos] = hi; g_atl[base1 + pos] = lo;
    }
}

// ---------------------------------------------------------------------------
// Kernel 3: output projection, bf16 3-term (Ah*Bh + Al*Bh + Ah*Bl).
// A read directly from global (fragment layout); B via cp.async 3-stage.
// ---------------------------------------------------------------------------
#define OSTG (2*64*32)                 // u32 per stage (Bh,Bl) = 4096
#define OUT_SMEM_BYTES (3*OSTG*4)      // 49152

__global__ __launch_bounds__(256, 2) void out_kernel(
    const float* __restrict__ bo, float* __restrict__ out)
{
    extern __shared__ __align__(16) uint32_t smo[];
    uint32_t smb = smem_u32(smo);

    int tid = threadIdx.x, lane = tid & 31, warp = tid >> 5;
    int g = lane >> 2, q = lane & 3;
    int e0 = blockIdx.x*64, r0 = blockIdx.y*128, wm = warp*16;

    int r8 = tid >> 3, seg = tid & 7;
    const char* srcH = (const char*)g_woh + (size_t)e0*(EE/2)*4;
    const char* srcL = (const char*)g_wol + (size_t)e0*(EE/2)*4;

    #pragma unroll
    for (int pf = 0; pf < 2; ++pf) {
        uint32_t base = smb + (pf % 3)*OSTG*4;
        #pragma unroll
        for (int t = 0; t < 2; ++t) {
            int row = r8 + 32*t;
            int sc = (seg ^ (row & 7))*16;
            uint32_t doff = row*128 + seg*16;
            CPA16(base + doff,        srcH + ((size_t)row*(EE/2) + pf*32)*4 + sc);
            CPA16(base + 8192 + doff, srcL + ((size_t)row*(EE/2) + pf*32)*4 + sc);
        }
        CPC();
    }

    const uint32_t* A0h = &g_ath[(size_t)(r0 + wm + g)*(EE/2)];
    const uint32_t* A1h = &g_ath[(size_t)(r0 + wm + g + 8)*(EE/2)];
    const uint32_t* A0l = &g_atl[(size_t)(r0 + wm + g)*(EE/2)];
    const uint32_t* A1l = &g_atl[(size_t)(r0 + wm + g + 8)*(EE/2)];

    int u0c = ((2*q) ^ g)*4;
    int u1c = ((2*q + 1) ^ g)*4;

    float oacc[8][4] = {};

    for (int j = 0; j < 16; ++j) {
        if (j < 15) { CPW(1); } else { CPW(0); }
        __syncthreads();
        if (j + 2 < 16) {
            uint32_t base = smb + ((j+2) % 3)*OSTG*4;
            #pragma unroll
            for (int t = 0; t < 2; ++t) {
                int row = r8 + 32*t;
                int sc = (seg ^ (row & 7))*16;
                uint32_t doff = row*128 + seg*16;
                CPA16(base + doff,        srcH + ((size_t)row*(EE/2) + (j+2)*32)*4 + sc);
                CPA16(base + 8192 + doff, srcL + ((size_t)row*(EE/2) + (j+2)*32)*4 + sc);
            }
            CPC();
        }

        const uint32_t* Bh = smo + (j % 3)*OSTG;
        const uint32_t* Bl = Bh + 2048;

        int ab = j*32 + q*8;
        uint4 Ah0 = __ldg((const uint4*)&A0h[ab]), Ah1 = __ldg((const uint4*)&A0h[ab + 4]);
        uint4 Gh0 = __ldg((const uint4*)&A1h[ab]), Gh1 = __ldg((const uint4*)&A1h[ab + 4]);
        uint4 Al0 = __ldg((const uint4*)&A0l[ab]), Al1 = __ldg((const uint4*)&A0l[ab + 4]);
        uint4 Gl0 = __ldg((const uint4*)&A1l[ab]), Gl1 = __ldg((const uint4*)&A1l[ab + 4]);

        #pragma unroll
        for (int nb = 0; nb < 8; ++nb) {
            int rb = (8*nb + g)*32;
            uint4 bh0 = *(const uint4*)&Bh[rb + u0c];
            uint4 bh1 = *(const uint4*)&Bh[rb + u1c];
            uint4 bl0 = *(const uint4*)&Bl[rb + u0c];
            uint4 bl1 = *(const uint4*)&Bl[rb + u1c];
            mma_bf16(oacc[nb], Ah0.x, Gh0.x, Ah0.y, Gh0.y, bh0.x, bh0.y);
            mma_bf16(oacc[nb], Al0.x, Gl0.x, Al0.y, Gl0.y, bh0.x, bh0.y);
            mma_bf16(oacc[nb], Ah0.x, Gh0.x, Ah0.y, Gh0.y, bl0.x, bl0.y);
            mma_bf16(oacc[nb], Ah0.z, Gh0.z, Ah0.w, Gh0.w, bh0.z, bh0.w);
            mma_bf16(oacc[nb], Al0.z, Gl0.z, Al0.w, Gl0.w, bh0.z, bh0.w);
            mma_bf16(oacc[nb], Ah0.z, Gh0.z, Ah0.w, Gh0.w, bl0.z, bl0.w);
            mma_bf16(oacc[nb], Ah1.x, Gh1.x, Ah1.y, Gh1.y, bh1.x, bh1.y);
            mma_bf16(oacc[nb], Al1.x, Gl1.x, Al1.y, Gl1.y, bh1.x, bh1.y);
            mma_bf16(oacc[nb], Ah1.x, Gh1.x, Ah1.y, Gh1.y, bl1.x, bl1.y);
            mma_bf16(oacc[nb], Ah1.z, Gh1.z, Ah1.w, Gh1.w, bh1.z, bh1.w);
            mma_bf16(oacc[nb], Al1.z, Gl1.z, Al1.w, Gl1.w, bh1.z, bh1.w);
            mma_bf16(oacc[nb], Ah1.z, Gh1.z, Ah1.w, Gh1.w, bl1.z, bl1.w);
        }
    }

    float* o0 = &out[(size_t)(r0 + wm + g)*EE + e0];
    float* o1 = &out[(size_t)(r0 + wm + g + 8)*EE + e0];
    #pragma unroll
    for (int nb = 0; nb < 8; ++nb) {
        int c = nb*8 + 2*q;
        float b0 = bo[e0 + c], b1 = bo[e0 + c + 1];
        o0[c] = oacc[nb][0] + b0; o0[c+1] = oacc[nb][1] + b1;
        o1[c] = oacc[nb][2] + b0; o1[c+1] = oacc[nb][3] + b1;
    }
}

// ---------------------------------------------------------------------------
extern "C" void kernel_launch(void* const* d_in, const int* in_sizes, int n_in,
                              void* d_out, int out_size)
{
    const float* x    = (const float*)d_in[0];
    const float* mask = (const float*)d_in[1];
    const float* Wq   = (const float*)d_in[2];
    const float* bq   = (const float*)d_in[3];
    const float* Wk   = (const float*)d_in[4];
    const float* bk   = (const float*)d_in[5];
    const float* Wv   = (const float*)d_in[6];
    const float* bv   = (const float*)d_in[7];
    const float* Wo   = (const float*)d_in[8];
    const float* bo   = (const float*)d_in[9];
    float* out = (float*)d_out;

    cudaFuncSetAttribute(qkv_kernel,  cudaFuncAttributeMaxDynamicSharedMemorySize, QKV_SMEM_BYTES);
    cudaFuncSetAttribute(attn_kernel, cudaFuncAttributeMaxDynamicSharedMemorySize, ATTN_SMEM_BYTES);
    cudaFuncSetAttribute(out_kernel,  cudaFuncAttributeMaxDynamicSharedMemorySize, OUT_SMEM_BYTES);

    wo_pack<<<dim3(EE/64, EE/64), 256>>>(Wo);
    qkv_kernel<<<dim3(BH, SS/128), 256, QKV_SMEM_BYTES>>>(x, Wq, bq, Wk, bk, Wv, bv);
    attn_kernel<<<dim3(BH, SS/128), 256, ATTN_SMEM_BYTES>>>(mask);
    out_kernel<<<dim3(EE/64, (BB*SS)/128), 256, OUT_SMEM_BYTES>>>(bo, out);
}

// round 11
// speedup vs baseline: 1.9486x; 1.0083x over previous
#include <cuda_runtime.h>
#include <cuda_bf16.h>
#include <math.h>
#include <cstdint>

#define BB 2
#define SS 2048
#define EE 1024
#define HH 16
#define HD 64
#define BH (BB*HH)
#define SCALE_L2E 0.18033688f   // 0.125 * log2(e); attention uses exp2

// Scratch (16B-aligned: uint4 / cp.async sources)
static __device__ __align__(16) uint32_t g_qb[(size_t)BH*SS*32];
static __device__ __align__(16) uint32_t g_kb[(size_t)BH*SS*32];
static __device__ __align__(16) uint32_t g_vbh[(size_t)BH*64*(SS/2)];
static __device__ __align__(16) uint32_t g_vbl[(size_t)BH*64*(SS/2)];
static __device__ __align__(16) uint32_t g_ath[(size_t)BB*SS*(EE/2)];
static __device__ __align__(16) uint32_t g_atl[(size_t)BB*SS*(EE/2)];
static __device__ __align__(16) uint32_t g_woh[(size_t)EE*(EE/2)];
static __device__ __align__(16) uint32_t g_wol[(size_t)EE*(EE/2)];

__device__ __forceinline__ uint32_t f2tf32(float x) {
    uint32_t r; asm("cvt.rna.tf32.f32 %0, %1;" : "=r"(r) : "f"(x)); return r;
}
__device__ __forceinline__ float frna(float x) { return __uint_as_float(f2tf32(x)); }
__device__ __forceinline__ uint32_t pack_bf16(float a, float b) {
    __nv_bfloat162 h = __floats2bfloat162_rn(a, b);
    return *reinterpret_cast<uint32_t*>(&h);
}
__device__ __forceinline__ void split_pack(float a, float b, uint32_t& hi, uint32_t& lo) {
    __nv_bfloat162 h = __floats2bfloat162_rn(a, b);
    lo = pack_bf16(a - __bfloat162float(h.x), b - __bfloat162float(h.y));
    hi = *reinterpret_cast<uint32_t*>(&h);
}
__device__ __forceinline__ uint32_t smem_u32(const void* p) {
    uint32_t a;
    asm("{ .reg .u64 t; cvta.to.shared.u64 t, %1; cvt.u32.u64 %0, t; }" : "=r"(a) : "l"(p));
    return a;
}
#define CPA16(d, s) asm volatile("cp.async.ca.shared.global [%0], [%1], 16;" :: "r"(d), "l"(s) : "memory")
#define CPC()       asm volatile("cp.async.commit_group;" ::: "memory")
#define CPW(n)      asm volatile("cp.async.wait_group %0;" :: "n"(n) : "memory")

__device__ __forceinline__ void mma_tf32(float c[4], float a0, float a1, float a2, float a3,
                                         float b0, float b1) {
    asm volatile("mma.sync.aligned.m16n8k8.row.col.f32.tf32.tf32.f32 "
        "{%0,%1,%2,%3}, {%4,%5,%6,%7}, {%8,%9}, {%0,%1,%2,%3};"
        : "+f"(c[0]), "+f"(c[1]), "+f"(c[2]), "+f"(c[3])
        : "r"(__float_as_uint(a0)), "r"(__float_as_uint(a1)),
          "r"(__float_as_uint(a2)), "r"(__float_as_uint(a3)),
          "r"(__float_as_uint(b0)), "r"(__float_as_uint(b1)));
}
__device__ __forceinline__ void mma_bf16(float c[4], uint32_t a0, uint32_t a1, uint32_t a2,
                                         uint32_t a3, uint32_t b0, uint32_t b1) {
    asm volatile("mma.sync.aligned.m16n8k16.row.col.f32.bf16.bf16.f32 "
        "{%0,%1,%2,%3}, {%4,%5,%6,%7}, {%8,%9}, {%0,%1,%2,%3};"
        : "+f"(c[0]), "+f"(c[1]), "+f"(c[2]), "+f"(c[3])
        : "r"(a0), "r"(a1), "r"(a2), "r"(a3), "r"(b0), "r"(b1));
}

// ---------------------------------------------------------------------------
// Kernel 1 (fused): blocks [0,512) = QKV projection; [512,768) = Wo pack.
// ---------------------------------------------------------------------------
#define QKV_SMEM_BYTES ((128*68 + 3*64*72)*4)

__global__ __launch_bounds__(256, 2) void qkv_wo_kernel(
    const float* __restrict__ x,
    const float* __restrict__ Wq, const float* __restrict__ bq,
    const float* __restrict__ Wk, const float* __restrict__ bk,
    const float* __restrict__ Wv, const float* __restrict__ bv,
    const float* __restrict__ Wo)
{
    extern __shared__ __align__(16) float smf[];
    int tid = threadIdx.x;
    int blk = blockIdx.x;

    if (blk >= 512) {   // ---- Wo pack ----
        int wid = blk - 512;
        int k0 = (wid & 15)*64, n0 = (wid >> 4)*64;
        float (*t)[65] = (float(*)[65])smf;
        for (int idx = tid; idx < 4096; idx += 256) {
            int ki = idx >> 6, n = idx & 63;
            t[ki][n] = Wo[(size_t)(k0 + ki)*EE + n0 + n];
        }
        __syncthreads();
        int nl = tid >> 2, qq = tid & 3;
        uint32_t hi[8], lo[8];
        #pragma unroll
        for (int j = 0; j < 8; ++j) {
            int pr = 4*j + qq;
            split_pack(t[2*pr][nl], t[2*pr + 1][nl], hi[j], lo[j]);
        }
        size_t ob = (size_t)(n0 + nl)*(EE/2) + (k0 >> 6)*32 + qq*8;
        *(uint4*)&g_woh[ob]     = make_uint4(hi[0], hi[1], hi[2], hi[3]);
        *(uint4*)&g_woh[ob + 4] = make_uint4(hi[4], hi[5], hi[6], hi[7]);
        *(uint4*)&g_wol[ob]     = make_uint4(lo[0], lo[1], lo[2], lo[3]);
        *(uint4*)&g_wol[ob + 4] = make_uint4(lo[4], lo[5], lo[6], lo[7]);
        return;
    }

    // ---- QKV ----
    float* At = smf;
    float* Ws = smf + 128*68;
    float* Vt = smf + 128*68;     // overlay after Ws reads done

    int lane = tid & 31, warp = tid >> 5;
    int g = lane >> 2, q = lane & 3;
    int bh = blk & 31, b = bh >> 4, h = bh & 15;
    int s0 = (blk >> 5) * 128, wm = warp * 16;

    for (int idx = tid; idx < 2048; idx += 256) {
        int row = idx >> 4, c4 = (idx & 15)*4;
        *(float4*)&At[row*68 + c4] = *(const float4*)&x[((size_t)b*SS + s0 + row)*EE + h*HD + c4];
    }
    const float* Wp[3] = {Wq, Wk, Wv};
    for (int w = 0; w < 3; ++w)
        for (int idx = tid; idx < 1024; idx += 256) {
            int row = idx >> 4, c4 = (idx & 15)*4;
            *(float4*)&Ws[w*64*72 + row*72 + c4] = *(const float4*)&Wp[w][(size_t)row*64 + c4];
        }
    __syncthreads();

    int r0g = s0 + wm + g, r1g = s0 + wm + g + 8;
    const float* bp[3] = {bq, bk, bv};

    for (int w = 0; w < 3; ++w) {
        float acc[8][4] = {};
        const float* B = &Ws[w*64*72];
        #pragma unroll
        for (int kk = 0; kk < 8; ++kk) {
            float a0 = frna(At[(wm + g)*68 + kk*8 + q]);
            float a1 = frna(At[(wm + g + 8)*68 + kk*8 + q]);
            float a2 = frna(At[(wm + g)*68 + kk*8 + q + 4]);
            float a3 = frna(At[(wm + g + 8)*68 + kk*8 + q + 4]);
            #pragma unroll
            for (int nb = 0; nb < 8; ++nb) {
                float b0 = frna(B[(kk*8 + q)*72 + nb*8 + g]);
                float b1 = frna(B[(kk*8 + q + 4)*72 + nb*8 + g]);
                mma_tf32(acc[nb], a0, a1, a2, a3, b0, b1);
            }
        }

        if (w == 0) {
            #pragma unroll
            for (int nb = 0; nb < 8; ++nb) {
                int c = nb*8 + 2*q;
                float b0 = bp[0][c], b1 = bp[0][c+1];
                g_qb[((size_t)bh*SS + r0g)*32 + q*8 + nb] = pack_bf16((acc[nb][0]+b0)*SCALE_L2E, (acc[nb][1]+b1)*SCALE_L2E);
                g_qb[((size_t)bh*SS + r1g)*32 + q*8 + nb] = pack_bf16((acc[nb][2]+b0)*SCALE_L2E, (acc[nb][3]+b1)*SCALE_L2E);
            }
        } else if (w == 1) {
            #pragma unroll
            for (int nb = 0; nb < 8; ++nb) {
                int c = nb*8 + 2*q;
                float b0 = bp[1][c], b1 = bp[1][c+1];
                g_kb[((size_t)bh*SS + r0g)*32 + q*8 + nb] = pack_bf16(acc[nb][0]+b0, acc[nb][1]+b1);
                g_kb[((size_t)bh*SS + r1g)*32 + q*8 + nb] = pack_bf16(acc[nb][2]+b0, acc[nb][3]+b1);
            }
        } else {
            __syncthreads();
            int rl0 = wm + g, rl1 = wm + g + 8;
            #pragma unroll
            for (int nb = 0; nb < 8; ++nb) {
                int c = nb*8 + 2*q;
                float b0 = bp[2][c], b1 = bp[2][c+1];
                Vt[rl0*65 + c] = acc[nb][0]+b0; Vt[rl0*65 + c+1] = acc[nb][1]+b1;
                Vt[rl1*65 + c] = acc[nb][2]+b0; Vt[rl1*65 + c+1] = acc[nb][3]+b1;
            }
            __syncthreads();
            int v = tid & 63, idx2 = tid >> 6, tl = idx2 >> 1, half = idx2 & 1;
            uint32_t hi[16], lo[16];
            #pragma unroll
            for (int j = 0; j < 16; ++j) {
                int pos = half*16 + j;
                int qv = pos >> 3, kk = (pos & 7) >> 1, hh = pos & 1;
                int sl = tl*64 + 2*(8*kk + 4*hh + qv);
                split_pack(Vt[sl*65 + v], Vt[(sl+1)*65 + v], hi[j], lo[j]);
            }
            size_t ob = ((size_t)bh*64 + v)*(SS/2) + (s0 >> 1) + tl*32 + half*16;
            #pragma unroll
            for (int u = 0; u < 4; ++u) {
                *(uint4*)&g_vbh[ob + 4*u] = make_uint4(hi[4*u], hi[4*u+1], hi[4*u+2], hi[4*u+3]);
                *(uint4*)&g_vbl[ob + 4*u] = make_uint4(lo[4*u], lo[4*u+1], lo[4*u+2], lo[4*u+3]);
            }
        }
    }
}

// ---------------------------------------------------------------------------
// Kernel 2: attention, bf16 mma, P-in-register, cp.async 3-stage pipeline.
// ---------------------------------------------------------------------------
#define SSTG (3*64*32)
#define ATTN_SMEM_BYTES (3*SSTG*4)

__global__ __launch_bounds__(256, 2) void attn_kernel(const float* __restrict__ mask)
{
    extern __shared__ __align__(16) uint32_t smu[];
    uint32_t smb = smem_u32(smu);

    int tid = threadIdx.x, lane = tid & 31, warp = tid >> 5;
    int g = lane >> 2, q = lane & 3;
    int bh = blockIdx.x, b = bh >> 4, h = bh & 15;
    int q0 = blockIdx.y * 128, wr = q0 + warp*16;

    int r8 = tid >> 3, seg = tid & 7;
    const char* srcK = (const char*)g_kb  + ((size_t)bh*SS)*128;
    const char* srcH = (const char*)g_vbh + ((size_t)bh*64)*(SS/2)*4;
    const char* srcL = (const char*)g_vbl + ((size_t)bh*64)*(SS/2)*4;

    #pragma unroll
    for (int pf = 0; pf < 2; ++pf) {
        int s0 = pf*64;
        uint32_t base = smb + (pf % 3)*SSTG*4;
        #pragma unroll
        for (int t = 0; t < 2; ++t) {
            int row = r8 + 32*t;
            int sc = (seg ^ (row & 7))*16;
            uint32_t doff = row*128 + seg*16;
            CPA16(base + doff,            srcK + (size_t)(s0+row)*128 + sc);
            CPA16(base + 8192 + doff,     srcH + ((size_t)row*(SS/2) + (s0>>1))*4 + sc);
            CPA16(base + 16384 + doff,    srcL + ((size_t)row*(SS/2) + (s0>>1))*4 + sc);
        }
        CPC();
    }

    uint32_t qa[8], qg[8];
    {
        const uint4* p0 = (const uint4*)&g_qb[((size_t)bh*SS + wr + g)*32 + q*8];
        const uint4* p1 = (const uint4*)&g_qb[((size_t)bh*SS + wr + g + 8)*32 + q*8];
        uint4 u0 = p0[0], u1 = p0[1], v0 = p1[0], v1 = p1[1];
        qa[0]=u0.x; qa[1]=u0.y; qa[2]=u0.z; qa[3]=u0.w; qa[4]=u1.x; qa[5]=u1.y; qa[6]=u1.z; qa[7]=u1.w;
        qg[0]=v0.x; qg[1]=v0.y; qg[2]=v0.z; qg[3]=v0.w; qg[4]=v1.x; qg[5]=v1.y; qg[6]=v1.z; qg[7]=v1.w;
    }

    float oacc[8][4] = {};
    float lsum0 = 0.f, lsum1 = 0.f;
    const float* mrow0 = &mask[(size_t)(wr + g)*SS];
    const float* mrow1 = &mask[(size_t)(wr + g + 8)*SS];
    int u0c = ((2*q) ^ g)*4;
    int u1c = ((2*q + 1) ^ g)*4;

    for (int jt = 0; jt < 32; ++jt) {
        if (jt < 31) { CPW(1); } else { CPW(0); }
        __syncthreads();
        if (jt + 2 < 32) {
            int s0n = (jt+2)*64;
            uint32_t base = smb + ((jt+2) % 3)*SSTG*4;
            #pragma unroll
            for (int t = 0; t < 2; ++t) {
                int row = r8 + 32*t;
                int sc = (seg ^ (row & 7))*16;
                uint32_t doff = row*128 + seg*16;
                CPA16(base + doff,         srcK + (size_t)(s0n+row)*128 + sc);
                CPA16(base + 8192 + doff,  srcH + ((size_t)row*(SS/2) + (s0n>>1))*4 + sc);
                CPA16(base + 16384 + doff, srcL + ((size_t)row*(SS/2) + (s0n>>1))*4 + sc);
            }
            CPC();
        }

        const uint32_t* Kb = smu + (jt % 3)*SSTG;
        const uint32_t* Vh = Kb + 2048;
        const uint32_t* Vl = Kb + 4096;
        int s0 = jt*64;

        float sacc[8][4] = {};
        #pragma unroll
        for (int nb = 0; nb < 8; ++nb) {
            int rb = (8*nb + g)*32;
            uint4 k0 = *(const uint4*)&Kb[rb + u0c];
            uint4 k1 = *(const uint4*)&Kb[rb + u1c];
            mma_bf16(sacc[nb], qa[0], qg[0], qa[1], qg[1], k0.x, k0.y);
            mma_bf16(sacc[nb], qa[2], qg[2], qa[3], qg[3], k0.z, k0.w);
            mma_bf16(sacc[nb], qa[4], qg[4], qa[5], qg[5], k1.x, k1.y);
            mma_bf16(sacc[nb], qa[6], qg[6], qa[7], qg[7], k1.z, k1.w);
        }

        uint32_t ph[8], pg[8], pl[8], pm[8];
        float ps0 = 0.f, ps1 = 0.f;
        #pragma unroll
        for (int nb = 0; nb < 8; ++nb) {
            float2 m0 = __ldg((const float2*)&mrow0[s0 + 8*nb + 2*q]);
            float2 m1 = __ldg((const float2*)&mrow1[s0 + 8*nb + 2*q]);
            float p0 = exp2f(sacc[nb][0]*m0.x);
            float p1 = exp2f(sacc[nb][1]*m0.y);
            float p2 = exp2f(sacc[nb][2]*m1.x);
            float p3 = exp2f(sacc[nb][3]*m1.y);
            ps0 += p0 + p1; ps1 += p2 + p3;
            split_pack(p0, p1, ph[nb], pl[nb]);
            split_pack(p2, p3, pg[nb], pm[nb]);
        }
        ps0 += __shfl_xor_sync(0xffffffffu, ps0, 1);
        ps0 += __shfl_xor_sync(0xffffffffu, ps0, 2);
        ps1 += __shfl_xor_sync(0xffffffffu, ps1, 1);
        ps1 += __shfl_xor_sync(0xffffffffu, ps1, 2);
        lsum0 += ps0; lsum1 += ps1;

        #pragma unroll
        for (int nb = 0; nb < 8; ++nb) {
            int rb = (8*nb + g)*32;
            uint4 h0 = *(const uint4*)&Vh[rb + u0c];
            uint4 h1 = *(const uint4*)&Vh[rb + u1c];
            uint4 l0 = *(const uint4*)&Vl[rb + u0c];
            uint4 l1 = *(const uint4*)&Vl[rb + u1c];
            mma_bf16(oacc[nb], ph[0], pg[0], ph[1], pg[1], h0.x, h0.y);
            mma_bf16(oacc[nb], pl[0], pm[0], pl[1], pm[1], h0.x, h0.y);
            mma_bf16(oacc[nb], ph[0], pg[0], ph[1], pg[1], l0.x, l0.y);
            mma_bf16(oacc[nb], ph[2], pg[2], ph[3], pg[3], h0.z, h0.w);
            mma_bf16(oacc[nb], pl[2], pm[2], pl[3], pm[3], h0.z, h0.w);
            mma_bf16(oacc[nb], ph[2], pg[2], ph[3], pg[3], l0.z, l0.w);
            mma_bf16(oacc[nb], ph[4], pg[4], ph[5], pg[5], h1.x, h1.y);
            mma_bf16(oacc[nb], pl[4], pm[4], pl[5], pm[5], h1.x, h1.y);
            mma_bf16(oacc[nb], ph[4], pg[4], ph[5], pg[5], l1.x, l1.y);
            mma_bf16(oacc[nb], ph[6], pg[6], ph[7], pg[7], h1.z, h1.w);
            mma_bf16(oacc[nb], pl[6], pm[6], pl[7], pm[7], h1.z, h1.w);
            mma_bf16(oacc[nb], ph[6], pg[6], ph[7], pg[7], l1.z, l1.w);
        }
    }

    float inv0 = 1.f/lsum0, inv1 = 1.f/lsum1;
    size_t base0 = ((size_t)b*SS + wr + g)*(EE/2) + h*32;
    size_t base1 = ((size_t)b*SS + wr + g + 8)*(EE/2) + h*32;
    #pragma unroll
    for (int nb = 0; nb < 8; ++nb) {
        int pos = q*8 + nb;
        uint32_t hi, lo;
        split_pack(oacc[nb][0]*inv0, oacc[nb][1]*inv0, hi, lo);
        g_ath[base0 + pos] = hi; g_atl[base0 + pos] = lo;
        split_pack(oacc[nb][2]*inv1, oacc[nb][3]*inv1, hi, lo);
        g_ath[base1 + pos] = hi; g_atl[base1 + pos] = lo;
    }
}

// ---------------------------------------------------------------------------
// Kernel 3: output projection, bf16 3-term; A AND B through cp.async 2-stage.
// Stage layout (u32): Ah[0,4096) Al[4096,8192) Bh[8192,10240) Bl[10240,12288)
// ---------------------------------------------------------------------------
#define OSTG2 12288
#define OUT_SMEM_BYTES (2*OSTG2*4)     // 98304

__global__ __launch_bounds__(256, 2) void out_kernel(
    const float* __restrict__ bo, float* __restrict__ out)
{
    extern __shared__ __align__(16) uint32_t smo[];
    uint32_t smb = smem_u32(smo);

    int tid = threadIdx.x, lane = tid & 31, warp = tid >> 5;
    int g = lane >> 2, q = lane & 3;
    int e0 = blockIdx.x*64, r0 = blockIdx.y*128, wm = warp*16;

    int r8 = tid >> 3, seg = tid & 7;
    const char* srcAh = (const char*)g_ath + (size_t)r0*(EE/2)*4;
    const char* srcAl = (const char*)g_atl + (size_t)r0*(EE/2)*4;
    const char* srcBh = (const char*)g_woh + (size_t)e0*(EE/2)*4;
    const char* srcBl = (const char*)g_wol + (size_t)e0*(EE/2)*4;

    // prefetch chunk 0 into stage 0
    {
        uint32_t base = smb;
        #pragma unroll
        for (int t = 0; t < 4; ++t) {
            int row = r8 + 32*t;
            int sc = (seg ^ (row & 7))*16;
            uint32_t doff = row*128 + seg*16;
            CPA16(base + doff,         srcAh + ((size_t)row*(EE/2))*4 + sc);
            CPA16(base + 16384 + doff, srcAl + ((size_t)row*(EE/2))*4 + sc);
        }
        #pragma unroll
        for (int t = 0; t < 2; ++t) {
            int row = r8 + 32*t;
            int sc = (seg ^ (row & 7))*16;
            uint32_t doff = row*128 + seg*16;
            CPA16(base + 32768 + doff, srcBh + ((size_t)row*(EE/2))*4 + sc);
            CPA16(base + 40960 + doff, srcBl + ((size_t)row*(EE/2))*4 + sc);
        }
        CPC();
    }

    int u0c = ((2*q) ^ g)*4;
    int u1c = ((2*q + 1) ^ g)*4;
    int ra0 = (wm + g)*32, ra1 = (wm + g + 8)*32;

    float oacc[8][4] = {};

    for (int j = 0; j < 16; ++j) {
        CPW(0);
        __syncthreads();
        if (j + 1 < 16) {
            int kc = (j + 1)*32;
            uint32_t base = smb + ((j + 1) & 1)*OSTG2*4;
            #pragma unroll
            for (int t = 0; t < 4; ++t) {
                int row = r8 + 32*t;
                int sc = (seg ^ (row & 7))*16;
                uint32_t doff = row*128 + seg*16;
                CPA16(base + doff,         srcAh + ((size_t)row*(EE/2) + kc)*4 + sc);
                CPA16(base + 16384 + doff, srcAl + ((size_t)row*(EE/2) + kc)*4 + sc);
            }
            #pragma unroll
            for (int t = 0; t < 2; ++t) {
                int row = r8 + 32*t;
                int sc = (seg ^ (row & 7))*16;
                uint32_t doff = row*128 + seg*16;
                CPA16(base + 32768 + doff, srcBh + ((size_t)row*(EE/2) + kc)*4 + sc);
                CPA16(base + 40960 + doff, srcBl + ((size_t)row*(EE/2) + kc)*4 + sc);
            }
            CPC();
        }

        const uint32_t* Ahs = smo + (j & 1)*OSTG2;
        const uint32_t* Als = Ahs + 4096;
        const uint32_t* Bh  = Ahs + 8192;
        const uint32_t* Bl  = Ahs + 10240;

        uint4 Ah0 = *(const uint4*)&Ahs[ra0 + u0c], Ah1 = *(const uint4*)&Ahs[ra0 + u1c];
        uint4 Gh0 = *(const uint4*)&Ahs[ra1 + u0c], Gh1 = *(const uint4*)&Ahs[ra1 + u1c];
        uint4 Al0 = *(const uint4*)&Als[ra0 + u0c], Al1 = *(const uint4*)&Als[ra0 + u1c];
        uint4 Gl0 = *(const uint4*)&Als[ra1 + u0c], Gl1 = *(const uint4*)&Als[ra1 + u1c];

        #pragma unroll
        for (int nb = 0; nb < 8; ++nb) {
            int rb = (8*nb + g)*32;
            uint4 bh0 = *(const uint4*)&Bh[rb + u0c];
            uint4 bh1 = *(const uint4*)&Bh[rb + u1c];
            uint4 bl0 = *(const uint4*)&Bl[rb + u0c];
            uint4 bl1 = *(const uint4*)&Bl[rb + u1c];
            mma_bf16(oacc[nb], Ah0.x, Gh0.x, Ah0.y, Gh0.y, bh0.x, bh0.y);
            mma_bf16(oacc[nb], Al0.x, Gl0.x, Al0.y, Gl0.y, bh0.x, bh0.y);
            mma_bf16(oacc[nb], Ah0.x, Gh0.x, Ah0.y, Gh0.y, bl0.x, bl0.y);
            mma_bf16(oacc[nb], Ah0.z, Gh0.z, Ah0.w, Gh0.w, bh0.z, bh0.w);
            mma_bf16(oacc[nb], Al0.z, Gl0.z, Al0.w, Gl0.w, bh0.z, bh0.w);
            mma_bf16(oacc[nb], Ah0.z, Gh0.z, Ah0.w, Gh0.w, bl0.z, bl0.w);
            mma_bf16(oacc[nb], Ah1.x, Gh1.x, Ah1.y, Gh1.y, bh1.x, bh1.y);
            mma_bf16(oacc[nb], Al1.x, Gl1.x, Al1.y, Gl1.y, bh1.x, bh1.y);
            mma_bf16(oacc[nb], Ah1.x, Gh1.x, Ah1.y, Gh1.y, bl1.x, bl1.y);
            mma_bf16(oacc[nb], Ah1.z, Gh1.z, Ah1.w, Gh1.w, bh1.z, bh1.w);
            mma_bf16(oacc[nb], Al1.z, Gl1.z, Al1.w, Gl1.w, bh1.z, bh1.w);
            mma_bf16(oacc[nb], Ah1.z, Gh1.z, Ah1.w, Gh1.w, bl1.z, bl1.w);
        }
    }

    float* o0 = &out[(size_t)(r0 + wm + g)*EE + e0];
    float* o1 = &out[(size_t)(r0 + wm + g + 8)*EE + e0];
    #pragma unroll
    for (int nb = 0; nb < 8; ++nb) {
        int c = nb*8 + 2*q;
        float b0 = bo[e0 + c], b1 = bo[e0 + c + 1];
        o0[c] = oacc[nb][0] + b0; o0[c+1] = oacc[nb][1] + b1;
        o1[c] = oacc[nb][2] + b0; o1[c+1] = oacc[nb][3] + b1;
    }
}

// ---------------------------------------------------------------------------
extern "C" void kernel_launch(void* const* d_in, const int* in_sizes, int n_in,
                              void* d_out, int out_size)
{
    const float* x    = (const float*)d_in[0];
    const float* mask = (const float*)d_in[1];
    const float* Wq   = (const float*)d_in[2];
    const float* bq   = (const float*)d_in[3];
    const float* Wk   = (const float*)d_in[4];
    const float* bk   = (const float*)d_in[5];
    const float* Wv   = (const float*)d_in[6];
    const float* bv   = (const float*)d_in[7];
    const float* Wo   = (const float*)d_in[8];
    const float* bo   = (const float*)d_in[9];
    float* out = (float*)d_out;

    cudaFuncSetAttribute(qkv_wo_kernel, cudaFuncAttributeMaxDynamicSharedMemorySize, QKV_SMEM_BYTES);
    cudaFuncSetAttribute(attn_kernel,   cudaFuncAttributeMaxDynamicSharedMemorySize, ATTN_SMEM_BYTES);
    cudaFuncSetAttribute(out_kernel,    cudaFuncAttributeMaxDynamicSharedMemorySize, OUT_SMEM_BYTES);

    qkv_wo_kernel<<<768, 256, QKV_SMEM_BYTES>>>(x, Wq, bq, Wk, bk, Wv, bv, Wo);
    attn_kernel<<<dim3(BH, SS/128), 256, ATTN_SMEM_BYTES>>>(mask);
    out_kernel<<<dim3(EE/64, (BB*SS)/128), 256, OUT_SMEM_BYTES>>>(bo, out);
}

// round 12
// speedup vs baseline: 2.3266x; 1.1940x over previous
#include <cuda_runtime.h>
#include <cuda_bf16.h>
#include <cuda_fp16.h>
#include <math.h>
#include <cstdint>

#define BB 2
#define SS 2048
#define EE 1024
#define HH 16
#define HD 64
#define BH (BB*HH)
#define SCALE_L2E 0.18033688f   // 0.125 * log2(e); attention uses exp2

// Scratch (16B-aligned)
static __device__ __align__(16) uint32_t g_qb[(size_t)BH*SS*32];      // Q fp16x2, scaled
static __device__ __align__(16) uint32_t g_kb[(size_t)BH*SS*32];      // K fp16x2
static __device__ __align__(16) uint32_t g_vb[(size_t)BH*64*(SS/2)];  // V fp16x2, v-major
static __device__ __align__(16) uint32_t g_ath[(size_t)BB*SS*(EE/2)]; // att hi bf16x2, A-frag layout
static __device__ __align__(16) uint32_t g_atl[(size_t)BB*SS*(EE/2)]; // att lo
static __device__ __align__(16) uint32_t g_woh[(size_t)EE*(EE/2)];    // Wo^T hi bf16x2, B-frag layout
static __device__ __align__(16) uint32_t g_wol[(size_t)EE*(EE/2)];

__device__ __forceinline__ uint32_t f2tf32(float x) {
    uint32_t r; asm("cvt.rna.tf32.f32 %0, %1;" : "=r"(r) : "f"(x)); return r;
}
__device__ __forceinline__ float frna(float x) { return __uint_as_float(f2tf32(x)); }
__device__ __forceinline__ uint32_t pack_h2(float a, float b) {
    __half2 h = __floats2half2_rn(a, b);
    return *reinterpret_cast<uint32_t*>(&h);
}
__device__ __forceinline__ void split_pack(float a, float b, uint32_t& hi, uint32_t& lo) {
    __nv_bfloat162 h = __floats2bfloat162_rn(a, b);
    __nv_bfloat162 l = __floats2bfloat162_rn(a - __bfloat162float(h.x), b - __bfloat162float(h.y));
    hi = *reinterpret_cast<uint32_t*>(&h);
    lo = *reinterpret_cast<uint32_t*>(&l);
}
__device__ __forceinline__ float ex2(float x) {
    float r; asm("ex2.approx.ftz.f32 %0, %1;" : "=f"(r) : "f"(x)); return r;
}
__device__ __forceinline__ uint32_t smem_u32(const void* p) {
    uint32_t a;
    asm("{ .reg .u64 t; cvta.to.shared.u64 t, %1; cvt.u32.u64 %0, t; }" : "=r"(a) : "l"(p));
    return a;
}
#define CPA16(d, s) asm volatile("cp.async.ca.shared.global [%0], [%1], 16;" :: "r"(d), "l"(s) : "memory")
#define CPC()       asm volatile("cp.async.commit_group;" ::: "memory")
#define CPW(n)      asm volatile("cp.async.wait_group %0;" :: "n"(n) : "memory")

__device__ __forceinline__ void mma_tf32(float c[4], float a0, float a1, float a2, float a3,
                                         float b0, float b1) {
    asm volatile("mma.sync.aligned.m16n8k8.row.col.f32.tf32.tf32.f32 "
        "{%0,%1,%2,%3}, {%4,%5,%6,%7}, {%8,%9}, {%0,%1,%2,%3};"
        : "+f"(c[0]), "+f"(c[1]), "+f"(c[2]), "+f"(c[3])
        : "r"(__float_as_uint(a0)), "r"(__float_as_uint(a1)),
          "r"(__float_as_uint(a2)), "r"(__float_as_uint(a3)),
          "r"(__float_as_uint(b0)), "r"(__float_as_uint(b1)));
}
__device__ __forceinline__ void mma_bf16(float c[4], uint32_t a0, uint32_t a1, uint32_t a2,
                                         uint32_t a3, uint32_t b0, uint32_t b1) {
    asm volatile("mma.sync.aligned.m16n8k16.row.col.f32.bf16.bf16.f32 "
        "{%0,%1,%2,%3}, {%4,%5,%6,%7}, {%8,%9}, {%0,%1,%2,%3};"
        : "+f"(c[0]), "+f"(c[1]), "+f"(c[2]), "+f"(c[3])
        : "r"(a0), "r"(a1), "r"(a2), "r"(a3), "r"(b0), "r"(b1));
}
__device__ __forceinline__ void mma_f16(float c[4], uint32_t a0, uint32_t a1, uint32_t a2,
                                        uint32_t a3, uint32_t b0, uint32_t b1) {
    asm volatile("mma.sync.aligned.m16n8k16.row.col.f32.f16.f16.f32 "
        "{%0,%1,%2,%3}, {%4,%5,%6,%7}, {%8,%9}, {%0,%1,%2,%3};"
        : "+f"(c[0]), "+f"(c[1]), "+f"(c[2]), "+f"(c[3])
        : "r"(a0), "r"(a1), "r"(a2), "r"(a3), "r"(b0), "r"(b1));
}

// ---------------------------------------------------------------------------
// Kernel 1 (fused): blocks [0,512) = QKV projection (fp16 pack); [512,768) = Wo pack (bf16).
// ---------------------------------------------------------------------------
#define QKV_SMEM_BYTES ((128*68 + 3*64*72)*4)

__global__ __launch_bounds__(256, 2) void qkv_wo_kernel(
    const float* __restrict__ x,
    const float* __restrict__ Wq, const float* __restrict__ bq,
    const float* __restrict__ Wk, const float* __restrict__ bk,
    const float* __restrict__ Wv, const float* __restrict__ bv,
    const float* __restrict__ Wo)
{
    extern __shared__ __align__(16) float smf[];
    int tid = threadIdx.x;
    int blk = blockIdx.x;

    if (blk >= 512) {   // ---- Wo pack (bf16 hi/lo) ----
        int wid = blk - 512;
        int k0 = (wid & 15)*64, n0 = (wid >> 4)*64;
        float (*t)[65] = (float(*)[65])smf;
        for (int idx = tid; idx < 4096; idx += 256) {
            int ki = idx >> 6, n = idx & 63;
            t[ki][n] = Wo[(size_t)(k0 + ki)*EE + n0 + n];
        }
        __syncthreads();
        int nl = tid >> 2, qq = tid & 3;
        uint32_t hi[8], lo[8];
        #pragma unroll
        for (int j = 0; j < 8; ++j) {
            int pr = 4*j + qq;
            split_pack(t[2*pr][nl], t[2*pr + 1][nl], hi[j], lo[j]);
        }
        size_t ob = (size_t)(n0 + nl)*(EE/2) + (k0 >> 6)*32 + qq*8;
        *(uint4*)&g_woh[ob]     = make_uint4(hi[0], hi[1], hi[2], hi[3]);
        *(uint4*)&g_woh[ob + 4] = make_uint4(hi[4], hi[5], hi[6], hi[7]);
        *(uint4*)&g_wol[ob]     = make_uint4(lo[0], lo[1], lo[2], lo[3]);
        *(uint4*)&g_wol[ob + 4] = make_uint4(lo[4], lo[5], lo[6], lo[7]);
        return;
    }

    // ---- QKV ----
    float* At = smf;
    float* Ws = smf + 128*68;
    float* Vt = smf + 128*68;     // overlay after Ws reads done

    int lane = tid & 31, warp = tid >> 5;
    int g = lane >> 2, q = lane & 3;
    int bh = blk & 31, b = bh >> 4, h = bh & 15;
    int s0 = (blk >> 5) * 128, wm = warp * 16;

    for (int idx = tid; idx < 2048; idx += 256) {
        int row = idx >> 4, c4 = (idx & 15)*4;
        *(float4*)&At[row*68 + c4] = *(const float4*)&x[((size_t)b*SS + s0 + row)*EE + h*HD + c4];
    }
    const float* Wp[3] = {Wq, Wk, Wv};
    for (int w = 0; w < 3; ++w)
        for (int idx = tid; idx < 1024; idx += 256) {
            int row = idx >> 4, c4 = (idx & 15)*4;
            *(float4*)&Ws[w*64*72 + row*72 + c4] = *(const float4*)&Wp[w][(size_t)row*64 + c4];
        }
    __syncthreads();

    int r0g = s0 + wm + g, r1g = s0 + wm + g + 8;
    const float* bp[3] = {bq, bk, bv};

    for (int w = 0; w < 3; ++w) {
        float acc[8][4] = {};
        const float* B = &Ws[w*64*72];
        #pragma unroll
        for (int kk = 0; kk < 8; ++kk) {
            float a0 = frna(At[(wm + g)*68 + kk*8 + q]);
            float a1 = frna(At[(wm + g + 8)*68 + kk*8 + q]);
            float a2 = frna(At[(wm + g)*68 + kk*8 + q + 4]);
            float a3 = frna(At[(wm + g + 8)*68 + kk*8 + q + 4]);
            #pragma unroll
            for (int nb = 0; nb < 8; ++nb) {
                float b0 = frna(B[(kk*8 + q)*72 + nb*8 + g]);
                float b1 = frna(B[(kk*8 + q + 4)*72 + nb*8 + g]);
                mma_tf32(acc[nb], a0, a1, a2, a3, b0, b1);
            }
        }

        if (w == 0) {
            #pragma unroll
            for (int nb = 0; nb < 8; ++nb) {
                int c = nb*8 + 2*q;
                float b0 = bp[0][c], b1 = bp[0][c+1];
                g_qb[((size_t)bh*SS + r0g)*32 + q*8 + nb] = pack_h2((acc[nb][0]+b0)*SCALE_L2E, (acc[nb][1]+b1)*SCALE_L2E);
                g_qb[((size_t)bh*SS + r1g)*32 + q*8 + nb] = pack_h2((acc[nb][2]+b0)*SCALE_L2E, (acc[nb][3]+b1)*SCALE_L2E);
            }
        } else if (w == 1) {
            #pragma unroll
            for (int nb = 0; nb < 8; ++nb) {
                int c = nb*8 + 2*q;
                float b0 = bp[1][c], b1 = bp[1][c+1];
                g_kb[((size_t)bh*SS + r0g)*32 + q*8 + nb] = pack_h2(acc[nb][0]+b0, acc[nb][1]+b1);
                g_kb[((size_t)bh*SS + r1g)*32 + q*8 + nb] = pack_h2(acc[nb][2]+b0, acc[nb][3]+b1);
            }
        } else {
            __syncthreads();
            int rl0 = wm + g, rl1 = wm + g + 8;
            #pragma unroll
            for (int nb = 0; nb < 8; ++nb) {
                int c = nb*8 + 2*q;
                float b0 = bp[2][c], b1 = bp[2][c+1];
                Vt[rl0*65 + c] = acc[nb][0]+b0; Vt[rl0*65 + c+1] = acc[nb][1]+b1;
                Vt[rl1*65 + c] = acc[nb][2]+b0; Vt[rl1*65 + c+1] = acc[nb][3]+b1;
            }
            __syncthreads();
            int v = tid & 63, idx2 = tid >> 6, tl = idx2 >> 1, half = idx2 & 1;
            uint32_t hv[16];
            #pragma unroll
            for (int j = 0; j < 16; ++j) {
                int pos = half*16 + j;
                int qv = pos >> 3, kk = (pos & 7) >> 1, hh = pos & 1;
                int sl = tl*64 + 2*(8*kk + 4*hh + qv);
                hv[j] = pack_h2(Vt[sl*65 + v], Vt[(sl+1)*65 + v]);
            }
            size_t ob = ((size_t)bh*64 + v)*(SS/2) + (s0 >> 1) + tl*32 + half*16;
            #pragma unroll
            for (int u = 0; u < 4; ++u)
                *(uint4*)&g_vb[ob + 4*u] = make_uint4(hv[4*u], hv[4*u+1], hv[4*u+2], hv[4*u+3]);
        }
    }
}

// ---------------------------------------------------------------------------
// Kernel 2: attention, fp16 mma (QK 1x, PV 1x), cp.async 3-stage pipeline.
// Stage (u32): K[0,2048) V[2048,4096).  XOR-16B-chunk swizzle.
// ---------------------------------------------------------------------------
#define SSTG (2*64*32)                  // 4096 u32 = 16KB
#define ATTN_SMEM_BYTES (3*SSTG*4)      // 49152

__global__ __launch_bounds__(256, 2) void attn_kernel(const float* __restrict__ mask)
{
    extern __shared__ __align__(16) uint32_t smu[];
    uint32_t smb = smem_u32(smu);

    int tid = threadIdx.x, lane = tid & 31, warp = tid >> 5;
    int g = lane >> 2, q = lane & 3;
    int bh = blockIdx.x, b = bh >> 4, h = bh & 15;
    int q0 = blockIdx.y * 128, wr = q0 + warp*16;

    int r8 = tid >> 3, seg = tid & 7;
    const char* srcK = (const char*)g_kb + ((size_t)bh*SS)*128;
    const char* srcV = (const char*)g_vb + ((size_t)bh*64)*(SS/2)*4;

    #pragma unroll
    for (int pf = 0; pf < 2; ++pf) {
        int s0 = pf*64;
        uint32_t base = smb + (pf % 3)*SSTG*4;
        #pragma unroll
        for (int t = 0; t < 2; ++t) {
            int row = r8 + 32*t;
            int sc = (seg ^ (row & 7))*16;
            uint32_t doff = row*128 + seg*16;
            CPA16(base + doff,        srcK + (size_t)(s0+row)*128 + sc);
            CPA16(base + 8192 + doff, srcV + ((size_t)row*(SS/2) + (s0>>1))*4 + sc);
        }
        CPC();
    }

    uint32_t qa[8], qg[8];
    {
        const uint4* p0 = (const uint4*)&g_qb[((size_t)bh*SS + wr + g)*32 + q*8];
        const uint4* p1 = (const uint4*)&g_qb[((size_t)bh*SS + wr + g + 8)*32 + q*8];
        uint4 u0 = p0[0], u1 = p0[1], v0 = p1[0], v1 = p1[1];
        qa[0]=u0.x; qa[1]=u0.y; qa[2]=u0.z; qa[3]=u0.w; qa[4]=u1.x; qa[5]=u1.y; qa[6]=u1.z; qa[7]=u1.w;
        qg[0]=v0.x; qg[1]=v0.y; qg[2]=v0.z; qg[3]=v0.w; qg[4]=v1.x; qg[5]=v1.y; qg[6]=v1.z; qg[7]=v1.w;
    }

    float oacc[8][4] = {};
    float lsum0 = 0.f, lsum1 = 0.f;
    const float* mrow0 = &mask[(size_t)(wr + g)*SS];
    const float* mrow1 = &mask[(size_t)(wr + g + 8)*SS];
    int u0c = ((2*q) ^ g)*4;
    int u1c = ((2*q + 1) ^ g)*4;

    for (int jt = 0; jt < 32; ++jt) {
        if (jt < 31) { CPW(1); } else { CPW(0); }
        __syncthreads();
        if (jt + 2 < 32) {
            int s0n = (jt+2)*64;
            uint32_t base = smb + ((jt+2) % 3)*SSTG*4;
            #pragma unroll
            for (int t = 0; t < 2; ++t) {
                int row = r8 + 32*t;
                int sc = (seg ^ (row & 7))*16;
                uint32_t doff = row*128 + seg*16;
                CPA16(base + doff,        srcK + (size_t)(s0n+row)*128 + sc);
                CPA16(base + 8192 + doff, srcV + ((size_t)row*(SS/2) + (s0n>>1))*4 + sc);
            }
            CPC();
        }

        const uint32_t* Kb = smu + (jt % 3)*SSTG;
        const uint32_t* Vs = Kb + 2048;
        int s0 = jt*64;

        // S = Q K^T
        float sacc[8][4] = {};
        #pragma unroll
        for (int nb = 0; nb < 8; ++nb) {
            int rb = (8*nb + g)*32;
            uint4 k0 = *(const uint4*)&Kb[rb + u0c];
            uint4 k1 = *(const uint4*)&Kb[rb + u1c];
            mma_f16(sacc[nb], qa[0], qg[0], qa[1], qg[1], k0.x, k0.y);
            mma_f16(sacc[nb], qa[2], qg[2], qa[3], qg[3], k0.z, k0.w);
            mma_f16(sacc[nb], qa[4], qg[4], qa[5], qg[5], k1.x, k1.y);
            mma_f16(sacc[nb], qa[6], qg[6], qa[7], qg[7], k1.z, k1.w);
        }

        // P = exp2(S * mask) -> fp16 A-fragments
        uint32_t ph[8], pg[8];
        float ps0 = 0.f, ps1 = 0.f;
        #pragma unroll
        for (int nb = 0; nb < 8; ++nb) {
            float2 m0 = __ldg((const float2*)&mrow0[s0 + 8*nb + 2*q]);
            float2 m1 = __ldg((const float2*)&mrow1[s0 + 8*nb + 2*q]);
            float p0 = ex2(sacc[nb][0]*m0.x);
            float p1 = ex2(sacc[nb][1]*m0.y);
            float p2 = ex2(sacc[nb][2]*m1.x);
            float p3 = ex2(sacc[nb][3]*m1.y);
            ps0 += p0 + p1; ps1 += p2 + p3;
            ph[nb] = pack_h2(p0, p1);
            pg[nb] = pack_h2(p2, p3);
        }
        ps0 += __shfl_xor_sync(0xffffffffu, ps0, 1);
        ps0 += __shfl_xor_sync(0xffffffffu, ps0, 2);
        ps1 += __shfl_xor_sync(0xffffffffu, ps1, 1);
        ps1 += __shfl_xor_sync(0xffffffffu, ps1, 2);
        lsum0 += ps0; lsum1 += ps1;

        // O += P V
        #pragma unroll
        for (int nb = 0; nb < 8; ++nb) {
            int rb = (8*nb + g)*32;
            uint4 v0 = *(const uint4*)&Vs[rb + u0c];
            uint4 v1 = *(const uint4*)&Vs[rb + u1c];
            mma_f16(oacc[nb], ph[0], pg[0], ph[1], pg[1], v0.x, v0.y);
            mma_f16(oacc[nb], ph[2], pg[2], ph[3], pg[3], v0.z, v0.w);
            mma_f16(oacc[nb], ph[4], pg[4], ph[5], pg[5], v1.x, v1.y);
            mma_f16(oacc[nb], ph[6], pg[6], ph[7], pg[7], v1.z, v1.w);
        }
    }

    // epilogue: normalize, split-pack bf16, write in A-fragment layout
    float inv0 = 1.f/lsum0, inv1 = 1.f/lsum1;
    size_t base0 = ((size_t)b*SS + wr + g)*(EE/2) + h*32;
    size_t base1 = ((size_t)b*SS + wr + g + 8)*(EE/2) + h*32;
    #pragma unroll
    for (int nb = 0; nb < 8; ++nb) {
        int pos = q*8 + nb;
        uint32_t hi, lo;
        split_pack(oacc[nb][0]*inv0, oacc[nb][1]*inv0, hi, lo);
        g_ath[base0 + pos] = hi; g_atl[base0 + pos] = lo;
        split_pack(oacc[nb][2]*inv1, oacc[nb][3]*inv1, hi, lo);
        g_ath[base1 + pos] = hi; g_atl[base1 + pos] = lo;
    }
}

// ---------------------------------------------------------------------------
// Kernel 3: output projection, bf16 3-term; A and B through cp.async 2-stage.
// Stage layout (u32): Ah[0,4096) Al[4096,8192) Bh[8192,10240) Bl[10240,12288)
// ---------------------------------------------------------------------------
#define OSTG2 12288
#define OUT_SMEM_BYTES (2*OSTG2*4)

__global__ __launch_bounds__(256, 2) void out_kernel(
    const float* __restrict__ bo, float* __restrict__ out)
{
    extern __shared__ __align__(16) uint32_t smo[];
    uint32_t smb = smem_u32(smo);

    int tid = threadIdx.x, lane = tid & 31, warp = tid >> 5;
    int g = lane >> 2, q = lane & 3;
    int e0 = blockIdx.x*64, r0 = blockIdx.y*128, wm = warp*16;

    int r8 = tid >> 3, seg = tid & 7;
    const char* srcAh = (const char*)g_ath + (size_t)r0*(EE/2)*4;
    const char* srcAl = (const char*)g_atl + (size_t)r0*(EE/2)*4;
    const char* srcBh = (const char*)g_woh + (size_t)e0*(EE/2)*4;
    const char* srcBl = (const char*)g_wol + (size_t)e0*(EE/2)*4;

    {
        uint32_t base = smb;
        #pragma unroll
        for (int t = 0; t < 4; ++t) {
            int row = r8 + 32*t;
            int sc = (seg ^ (row & 7))*16;
            uint32_t doff = row*128 + seg*16;
            CPA16(base + doff,         srcAh + ((size_t)row*(EE/2))*4 + sc);
            CPA16(base + 16384 + doff, srcAl + ((size_t)row*(EE/2))*4 + sc);
        }
        #pragma unroll
        for (int t = 0; t < 2; ++t) {
            int row = r8 + 32*t;
            int sc = (seg ^ (row & 7))*16;
            uint32_t doff = row*128 + seg*16;
            CPA16(base + 32768 + doff, srcBh + ((size_t)row*(EE/2))*4 + sc);
            CPA16(base + 40960 + doff, srcBl + ((size_t)row*(EE/2))*4 + sc);
        }
        CPC();
    }

    int u0c = ((2*q) ^ g)*4;
    int u1c = ((2*q + 1) ^ g)*4;
    int ra0 = (wm + g)*32, ra1 = (wm + g + 8)*32;

    float oacc[8][4] = {};

    for (int j = 0; j < 16; ++j) {
        CPW(0);
        __syncthreads();
        if (j + 1 < 16) {
            int kc = (j + 1)*32;
            uint32_t base = smb + ((j + 1) & 1)*OSTG2*4;
            #pragma unroll
            for (int t = 0; t < 4; ++t) {
                int row = r8 + 32*t;
                int sc = (seg ^ (row & 7))*16;
                uint32_t doff = row*128 + seg*16;
                CPA16(base + doff,         srcAh + ((size_t)row*(EE/2) + kc)*4 + sc);
                CPA16(base + 16384 + doff, srcAl + ((size_t)row*(EE/2) + kc)*4 + sc);
            }
            #pragma unroll
            for (int t = 0; t < 2; ++t) {
                int row = r8 + 32*t;
                int sc = (seg ^ (row & 7))*16;
                uint32_t doff = row*128 + seg*16;
                CPA16(base + 32768 + doff, srcBh + ((size_t)row*(EE/2) + kc)*4 + sc);
                CPA16(base + 40960 + doff, srcBl + ((size_t)row*(EE/2) + kc)*4 + sc);
            }
            CPC();
        }

        const uint32_t* Ahs = smo + (j & 1)*OSTG2;
        const uint32_t* Als = Ahs + 4096;
        const uint32_t* Bh  = Ahs + 8192;
        const uint32_t* Bl  = Ahs + 10240;

        uint4 Ah0 = *(const uint4*)&Ahs[ra0 + u0c], Ah1 = *(const uint4*)&Ahs[ra0 + u1c];
        uint4 Gh0 = *(const uint4*)&Ahs[ra1 + u0c], Gh1 = *(const uint4*)&Ahs[ra1 + u1c];
        uint4 Al0 = *(const uint4*)&Als[ra0 + u0c], Al1 = *(const uint4*)&Als[ra0 + u1c];
        uint4 Gl0 = *(const uint4*)&Als[ra1 + u0c], Gl1 = *(const uint4*)&Als[ra1 + u1c];

        #pragma unroll
        for (int nb = 0; nb < 8; ++nb) {
            int rb = (8*nb + g)*32;
            uint4 bh0 = *(const uint4*)&Bh[rb + u0c];
            uint4 bh1 = *(const uint4*)&Bh[rb + u1c];
            uint4 bl0 = *(const uint4*)&Bl[rb + u0c];
            uint4 bl1 = *(const uint4*)&Bl[rb + u1c];
            mma_bf16(oacc[nb], Ah0.x, Gh0.x, Ah0.y, Gh0.y, bh0.x, bh0.y);
            mma_bf16(oacc[nb], Al0.x, Gl0.x, Al0.y, Gl0.y, bh0.x, bh0.y);
            mma_bf16(oacc[nb], Ah0.x, Gh0.x, Ah0.y, Gh0.y, bl0.x, bl0.y);
            mma_bf16(oacc[nb], Ah0.z, Gh0.z, Ah0.w, Gh0.w, bh0.z, bh0.w);
            mma_bf16(oacc[nb], Al0.z, Gl0.z, Al0.w, Gl0.w, bh0.z, bh0.w);
            mma_bf16(oacc[nb], Ah0.z, Gh0.z, Ah0.w, Gh0.w, bl0.z, bl0.w);
            mma_bf16(oacc[nb], Ah1.x, Gh1.x, Ah1.y, Gh1.y, bh1.x, bh1.y);
            mma_bf16(oacc[nb], Al1.x, Gl1.x, Al1.y, Gl1.y, bh1.x, bh1.y);
            mma_bf16(oacc[nb], Ah1.x, Gh1.x, Ah1.y, Gh1.y, bl1.x, bl1.y);
            mma_bf16(oacc[nb], Ah1.z, Gh1.z, Ah1.w, Gh1.w, bh1.z, bh1.w);
            mma_bf16(oacc[nb], Al1.z, Gl1.z, Al1.w, Gl1.w, bh1.z, bh1.w);
            mma_bf16(oacc[nb], Ah1.z, Gh1.z, Ah1.w, Gh1.w, bl1.z, bl1.w);
        }
    }

    float* o0 = &out[(size_t)(r0 + wm + g)*EE + e0];
    float* o1 = &out[(size_t)(r0 + wm + g + 8)*EE + e0];
    #pragma unroll
    for (int nb = 0; nb < 8; ++nb) {
        int c = nb*8 + 2*q;
        float b0 = bo[e0 + c], b1 = bo[e0 + c + 1];
        o0[c] = oacc[nb][0] + b0; o0[c+1] = oacc[nb][1] + b1;
        o1[c] = oacc[nb][2] + b0; o1[c+1] = oacc[nb][3] + b1;
    }
}

// ---------------------------------------------------------------------------
extern "C" void kernel_launch(void* const* d_in, const int* in_sizes, int n_in,
                              void* d_out, int out_size)
{
    const float* x    = (const float*)d_in[0];
    const float* mask = (const float*)d_in[1];
    const float* Wq   = (const float*)d_in[2];
    const float* bq   = (const float*)d_in[3];
    const float* Wk   = (const float*)d_in[4];
    const float* bk   = (const float*)d_in[5];
    const float* Wv   = (const float*)d_in[6];
    const float* bv   = (const float*)d_in[7];
    const float* Wo   = (const float*)d_in[8];
    const float* bo   = (const float*)d_in[9];
    float* out = (float*)d_out;

    cudaFuncSetAttribute(qkv_wo_kernel, cudaFuncAttributeMaxDynamicSharedMemorySize, QKV_SMEM_BYTES);
    cudaFuncSetAttribute(attn_kernel,   cudaFuncAttributeMaxDynamicSharedMemorySize, ATTN_SMEM_BYTES);
    cudaFuncSetAttribute(out_kernel,    cudaFuncAttributeMaxDynamicSharedMemorySize, OUT_SMEM_BYTES);

    qkv_wo_kernel<<<768, 256, QKV_SMEM_BYTES>>>(x, Wq, bq, Wk, bk, Wv, bv, Wo);
    attn_kernel<<<dim3(BH, SS/128), 256, ATTN_SMEM_BYTES>>>(mask);
    out_kernel<<<dim3(EE/64, (BB*SS)/128), 256, OUT_SMEM_BYTES>>>(bo, out);
}

// round 13
// speedup vs baseline: 2.9875x; 1.2840x over previous
#include <cuda_runtime.h>
#include <cuda_bf16.h>
#include <cuda_fp16.h>
#include <math.h>
#include <cstdint>

#define BB 2
#define SS 2048
#define EE 1024
#define HH 16
#define HD 64
#define BH (BB*HH)
#define SCALE_L2E 0.18033688f   // 0.125 * log2(e); attention uses exp2

// Scratch (16B-aligned)
static __device__ __align__(16) uint32_t g_qb[(size_t)BH*SS*32];      // Q fp16x2, scaled
static __device__ __align__(16) uint32_t g_kb[(size_t)BH*SS*32];      // K fp16x2
static __device__ __align__(16) uint32_t g_vb[(size_t)BH*64*(SS/2)];  // V fp16x2, v-major
static __device__ __align__(16) uint32_t g_at[(size_t)BB*SS*(EE/2)];  // att fp16x2, A-frag layout
static __device__ __align__(16) uint32_t g_wo[(size_t)EE*(EE/2)];     // Wo^T fp16x2, B-frag layout

__device__ __forceinline__ uint32_t f2tf32(float x) {
    uint32_t r; asm("cvt.rna.tf32.f32 %0, %1;" : "=r"(r) : "f"(x)); return r;
}
__device__ __forceinline__ float frna(float x) { return __uint_as_float(f2tf32(x)); }
__device__ __forceinline__ uint32_t pack_h2(float a, float b) {
    __half2 h = __floats2half2_rn(a, b);
    return *reinterpret_cast<uint32_t*>(&h);
}
__device__ __forceinline__ float ex2(float x) {
    float r; asm("ex2.approx.ftz.f32 %0, %1;" : "=f"(r) : "f"(x)); return r;
}
__device__ __forceinline__ uint32_t smem_u32(const void* p) {
    uint32_t a;
    asm("{ .reg .u64 t; cvta.to.shared.u64 t, %1; cvt.u32.u64 %0, t; }" : "=r"(a) : "l"(p));
    return a;
}
#define CPA16(d, s) asm volatile("cp.async.ca.shared.global [%0], [%1], 16;" :: "r"(d), "l"(s) : "memory")
#define CPC()       asm volatile("cp.async.commit_group;" ::: "memory")
#define CPW(n)      asm volatile("cp.async.wait_group %0;" :: "n"(n) : "memory")

__device__ __forceinline__ void mma_tf32(float c[4], float a0, float a1, float a2, float a3,
                                         float b0, float b1) {
    asm volatile("mma.sync.aligned.m16n8k8.row.col.f32.tf32.tf32.f32 "
        "{%0,%1,%2,%3}, {%4,%5,%6,%7}, {%8,%9}, {%0,%1,%2,%3};"
        : "+f"(c[0]), "+f"(c[1]), "+f"(c[2]), "+f"(c[3])
        : "r"(__float_as_uint(a0)), "r"(__float_as_uint(a1)),
          "r"(__float_as_uint(a2)), "r"(__float_as_uint(a3)),
          "r"(__float_as_uint(b0)), "r"(__float_as_uint(b1)));
}
__device__ __forceinline__ void mma_f16(float c[4], uint32_t a0, uint32_t a1, uint32_t a2,
                                        uint32_t a3, uint32_t b0, uint32_t b1) {
    asm volatile("mma.sync.aligned.m16n8k16.row.col.f32.f16.f16.f32 "
        "{%0,%1,%2,%3}, {%4,%5,%6,%7}, {%8,%9}, {%0,%1,%2,%3};"
        : "+f"(c[0]), "+f"(c[1]), "+f"(c[2]), "+f"(c[3])
        : "r"(a0), "r"(a1), "r"(a2), "r"(a3), "r"(b0), "r"(b1));
}

// ---------------------------------------------------------------------------
// Kernel 1 (fused): blocks [0,512) = QKV projection (fp16 pack);
//                   blocks [512,768) = Wo pack (fp16, B-frag layout).
// ---------------------------------------------------------------------------
#define QKV_SMEM_BYTES ((128*68 + 3*64*72)*4)

__global__ __launch_bounds__(256, 2) void qkv_wo_kernel(
    const float* __restrict__ x,
    const float* __restrict__ Wq, const float* __restrict__ bq,
    const float* __restrict__ Wk, const float* __restrict__ bk,
    const float* __restrict__ Wv, const float* __restrict__ bv,
    const float* __restrict__ Wo)
{
    extern __shared__ __align__(16) float smf[];
    int tid = threadIdx.x;
    int blk = blockIdx.x;

    if (blk >= 512) {   // ---- Wo pack (fp16 single) ----
        int wid = blk - 512;
        int k0 = (wid & 15)*64, n0 = (wid >> 4)*64;
        float (*t)[65] = (float(*)[65])smf;
        for (int idx = tid; idx < 4096; idx += 256) {
            int ki = idx >> 6, n = idx & 63;
            t[ki][n] = Wo[(size_t)(k0 + ki)*EE + n0 + n];
        }
        __syncthreads();
        int nl = tid >> 2, qq = tid & 3;
        uint32_t hv[8];
        #pragma unroll
        for (int j = 0; j < 8; ++j) {
            int pr = 4*j + qq;                     // logical pair, stored at pos qq*8+j
            hv[j] = pack_h2(t[2*pr][nl], t[2*pr + 1][nl]);
        }
        size_t ob = (size_t)(n0 + nl)*(EE/2) + (k0 >> 6)*32 + qq*8;
        *(uint4*)&g_wo[ob]     = make_uint4(hv[0], hv[1], hv[2], hv[3]);
        *(uint4*)&g_wo[ob + 4] = make_uint4(hv[4], hv[5], hv[6], hv[7]);
        return;
    }

    // ---- QKV ----
    float* At = smf;
    float* Ws = smf + 128*68;
    float* Vt = smf + 128*68;     // overlay after Ws reads done

    int lane = tid & 31, warp = tid >> 5;
    int g = lane >> 2, q = lane & 3;
    int bh = blk & 31, b = bh >> 4, h = bh & 15;
    int s0 = (blk >> 5) * 128, wm = warp * 16;

    for (int idx = tid; idx < 2048; idx += 256) {
        int row = idx >> 4, c4 = (idx & 15)*4;
        *(float4*)&At[row*68 + c4] = *(const float4*)&x[((size_t)b*SS + s0 + row)*EE + h*HD + c4];
    }
    const float* Wp[3] = {Wq, Wk, Wv};
    for (int w = 0; w < 3; ++w)
        for (int idx = tid; idx < 1024; idx += 256) {
            int row = idx >> 4, c4 = (idx & 15)*4;
            *(float4*)&Ws[w*64*72 + row*72 + c4] = *(const float4*)&Wp[w][(size_t)row*64 + c4];
        }
    __syncthreads();

    int r0g = s0 + wm + g, r1g = s0 + wm + g + 8;
    const float* bp[3] = {bq, bk, bv};

    for (int w = 0; w < 3; ++w) {
        float acc[8][4] = {};
        const float* B = &Ws[w*64*72];
        #pragma unroll
        for (int kk = 0; kk < 8; ++kk) {
            float a0 = frna(At[(wm + g)*68 + kk*8 + q]);
            float a1 = frna(At[(wm + g + 8)*68 + kk*8 + q]);
            float a2 = frna(At[(wm + g)*68 + kk*8 + q + 4]);
            float a3 = frna(At[(wm + g + 8)*68 + kk*8 + q + 4]);
            #pragma unroll
            for (int nb = 0; nb < 8; ++nb) {
                float b0 = frna(B[(kk*8 + q)*72 + nb*8 + g]);
                float b1 = frna(B[(kk*8 + q + 4)*72 + nb*8 + g]);
                mma_tf32(acc[nb], a0, a1, a2, a3, b0, b1);
            }
        }

        if (w == 0) {
            #pragma unroll
            for (int nb = 0; nb < 8; ++nb) {
                int c = nb*8 + 2*q;
                float b0 = bp[0][c], b1 = bp[0][c+1];
                g_qb[((size_t)bh*SS + r0g)*32 + q*8 + nb] = pack_h2((acc[nb][0]+b0)*SCALE_L2E, (acc[nb][1]+b1)*SCALE_L2E);
                g_qb[((size_t)bh*SS + r1g)*32 + q*8 + nb] = pack_h2((acc[nb][2]+b0)*SCALE_L2E, (acc[nb][3]+b1)*SCALE_L2E);
            }
        } else if (w == 1) {
            #pragma unroll
            for (int nb = 0; nb < 8; ++nb) {
                int c = nb*8 + 2*q;
                float b0 = bp[1][c], b1 = bp[1][c+1];
                g_kb[((size_t)bh*SS + r0g)*32 + q*8 + nb] = pack_h2(acc[nb][0]+b0, acc[nb][1]+b1);
                g_kb[((size_t)bh*SS + r1g)*32 + q*8 + nb] = pack_h2(acc[nb][2]+b0, acc[nb][3]+b1);
            }
        } else {
            __syncthreads();
            int rl0 = wm + g, rl1 = wm + g + 8;
            #pragma unroll
            for (int nb = 0; nb < 8; ++nb) {
                int c = nb*8 + 2*q;
                float b0 = bp[2][c], b1 = bp[2][c+1];
                Vt[rl0*65 + c] = acc[nb][0]+b0; Vt[rl0*65 + c+1] = acc[nb][1]+b1;
                Vt[rl1*65 + c] = acc[nb][2]+b0; Vt[rl1*65 + c+1] = acc[nb][3]+b1;
            }
            __syncthreads();
            int v = tid & 63, idx2 = tid >> 6, tl = idx2 >> 1, half = idx2 & 1;
            uint32_t hv[16];
            #pragma unroll
            for (int j = 0; j < 16; ++j) {
                int pos = half*16 + j;
                int qv = pos >> 3, kk = (pos & 7) >> 1, hh = pos & 1;
                int sl = tl*64 + 2*(8*kk + 4*hh + qv);
                hv[j] = pack_h2(Vt[sl*65 + v], Vt[(sl+1)*65 + v]);
            }
            size_t ob = ((size_t)bh*64 + v)*(SS/2) + (s0 >> 1) + tl*32 + half*16;
            #pragma unroll
            for (int u = 0; u < 4; ++u)
                *(uint4*)&g_vb[ob + 4*u] = make_uint4(hv[4*u], hv[4*u+1], hv[4*u+2], hv[4*u+3]);
        }
    }
}

// ---------------------------------------------------------------------------
// Kernel 2: attention, fp16 mma (QK 1x, PV 1x), cp.async 3-stage pipeline.
// Epilogue writes O as fp16x2 pairs in A-fragment layout (single array).
// ---------------------------------------------------------------------------
#define SSTG (2*64*32)                  // 4096 u32 = 16KB
#define ATTN_SMEM_BYTES (3*SSTG*4)      // 49152

__global__ __launch_bounds__(256, 2) void attn_kernel(const float* __restrict__ mask)
{
    extern __shared__ __align__(16) uint32_t smu[];
    uint32_t smb = smem_u32(smu);

    int tid = threadIdx.x, lane = tid & 31, warp = tid >> 5;
    int g = lane >> 2, q = lane & 3;
    int bh = blockIdx.x, b = bh >> 4, h = bh & 15;
    int q0 = blockIdx.y * 128, wr = q0 + warp*16;

    int r8 = tid >> 3, seg = tid & 7;
    const char* srcK = (const char*)g_kb + ((size_t)bh*SS)*128;
    const char* srcV = (const char*)g_vb + ((size_t)bh*64)*(SS/2)*4;

    #pragma unroll
    for (int pf = 0; pf < 2; ++pf) {
        int s0 = pf*64;
        uint32_t base = smb + (pf % 3)*SSTG*4;
        #pragma unroll
        for (int t = 0; t < 2; ++t) {
            int row = r8 + 32*t;
            int sc = (seg ^ (row & 7))*16;
            uint32_t doff = row*128 + seg*16;
            CPA16(base + doff,        srcK + (size_t)(s0+row)*128 + sc);
            CPA16(base + 8192 + doff, srcV + ((size_t)row*(SS/2) + (s0>>1))*4 + sc);
        }
        CPC();
    }

    uint32_t qa[8], qg[8];
    {
        const uint4* p0 = (const uint4*)&g_qb[((size_t)bh*SS + wr + g)*32 + q*8];
        const uint4* p1 = (const uint4*)&g_qb[((size_t)bh*SS + wr + g + 8)*32 + q*8];
        uint4 u0 = p0[0], u1 = p0[1], v0 = p1[0], v1 = p1[1];
        qa[0]=u0.x; qa[1]=u0.y; qa[2]=u0.z; qa[3]=u0.w; qa[4]=u1.x; qa[5]=u1.y; qa[6]=u1.z; qa[7]=u1.w;
        qg[0]=v0.x; qg[1]=v0.y; qg[2]=v0.z; qg[3]=v0.w; qg[4]=v1.x; qg[5]=v1.y; qg[6]=v1.z; qg[7]=v1.w;
    }

    float oacc[8][4] = {};
    float lsum0 = 0.f, lsum1 = 0.f;
    const float* mrow0 = &mask[(size_t)(wr + g)*SS];
    const float* mrow1 = &mask[(size_t)(wr + g + 8)*SS];
    int u0c = ((2*q) ^ g)*4;
    int u1c = ((2*q + 1) ^ g)*4;

    for (int jt = 0; jt < 32; ++jt) {
        if (jt < 31) { CPW(1); } else { CPW(0); }
        __syncthreads();
        if (jt + 2 < 32) {
            int s0n = (jt+2)*64;
            uint32_t base = smb + ((jt+2) % 3)*SSTG*4;
            #pragma unroll
            for (int t = 0; t < 2; ++t) {
                int row = r8 + 32*t;
                int sc = (seg ^ (row & 7))*16;
                uint32_t doff = row*128 + seg*16;
                CPA16(base + doff,        srcK + (size_t)(s0n+row)*128 + sc);
                CPA16(base + 8192 + doff, srcV + ((size_t)row*(SS/2) + (s0n>>1))*4 + sc);
            }
            CPC();
        }

        const uint32_t* Kb = smu + (jt % 3)*SSTG;
        const uint32_t* Vs = Kb + 2048;
        int s0 = jt*64;

        // S = Q K^T
        float sacc[8][4] = {};
        #pragma unroll
        for (int nb = 0; nb < 8; ++nb) {
            int rb = (8*nb + g)*32;
            uint4 k0 = *(const uint4*)&Kb[rb + u0c];
            uint4 k1 = *(const uint4*)&Kb[rb + u1c];
            mma_f16(sacc[nb], qa[0], qg[0], qa[1], qg[1], k0.x, k0.y);
            mma_f16(sacc[nb], qa[2], qg[2], qa[3], qg[3], k0.z, k0.w);
            mma_f16(sacc[nb], qa[4], qg[4], qa[5], qg[5], k1.x, k1.y);
            mma_f16(sacc[nb], qa[6], qg[6], qa[7], qg[7], k1.z, k1.w);
        }

        // P = exp2(S * mask) -> fp16 A-fragments
        uint32_t ph[8], pg[8];
        float ps0 = 0.f, ps1 = 0.f;
        #pragma unroll
        for (int nb = 0; nb < 8; ++nb) {
            float2 m0 = __ldg((const float2*)&mrow0[s0 + 8*nb + 2*q]);
            float2 m1 = __ldg((const float2*)&mrow1[s0 + 8*nb + 2*q]);
            float p0 = ex2(sacc[nb][0]*m0.x);
            float p1 = ex2(sacc[nb][1]*m0.y);
            float p2 = ex2(sacc[nb][2]*m1.x);
            float p3 = ex2(sacc[nb][3]*m1.y);
            ps0 += p0 + p1; ps1 += p2 + p3;
            ph[nb] = pack_h2(p0, p1);
            pg[nb] = pack_h2(p2, p3);
        }
        ps0 += __shfl_xor_sync(0xffffffffu, ps0, 1);
        ps0 += __shfl_xor_sync(0xffffffffu, ps0, 2);
        ps1 += __shfl_xor_sync(0xffffffffu, ps1, 1);
        ps1 += __shfl_xor_sync(0xffffffffu, ps1, 2);
        lsum0 += ps0; lsum1 += ps1;

        // O += P V
        #pragma unroll
        for (int nb = 0; nb < 8; ++nb) {
            int rb = (8*nb + g)*32;
            uint4 v0 = *(const uint4*)&Vs[rb + u0c];
            uint4 v1 = *(const uint4*)&Vs[rb + u1c];
            mma_f16(oacc[nb], ph[0], pg[0], ph[1], pg[1], v0.x, v0.y);
            mma_f16(oacc[nb], ph[2], pg[2], ph[3], pg[3], v0.z, v0.w);
            mma_f16(oacc[nb], ph[4], pg[4], ph[5], pg[5], v1.x, v1.y);
            mma_f16(oacc[nb], ph[6], pg[6], ph[7], pg[7], v1.z, v1.w);
        }
    }

    // epilogue: normalize, pack fp16, write in A-fragment layout (pos q*8+nb)
    float inv0 = 1.f/lsum0, inv1 = 1.f/lsum1;
    size_t base0 = ((size_t)b*SS + wr + g)*(EE/2) + h*32;
    size_t base1 = ((size_t)b*SS + wr + g + 8)*(EE/2) + h*32;
    #pragma unroll
    for (int nb = 0; nb < 8; ++nb) {
        int pos = q*8 + nb;
        g_at[base0 + pos] = pack_h2(oacc[nb][0]*inv0, oacc[nb][1]*inv0);
        g_at[base1 + pos] = pack_h2(oacc[nb][2]*inv1, oacc[nb][3]*inv1);
    }
}

// ---------------------------------------------------------------------------
// Kernel 3: output projection, fp16 single-term; A and B via cp.async 2-stage.
// Stage layout (u32): A[0,4096) B[4096,6144).  Chunk = 64 k-values.
// ---------------------------------------------------------------------------
#define OSTG3 6144
#define OUT_SMEM_BYTES (2*OSTG3*4)      // 49152

__global__ __launch_bounds__(256, 2) void out_kernel(
    const float* __restrict__ bo, float* __restrict__ out)
{
    extern __shared__ __align__(16) uint32_t smo[];
    uint32_t smb = smem_u32(smo);

    int tid = threadIdx.x, lane = tid & 31, warp = tid >> 5;
    int g = lane >> 2, q = lane & 3;
    int e0 = blockIdx.x*64, r0 = blockIdx.y*128, wm = warp*16;

    int r8 = tid >> 3, seg = tid & 7;
    const char* srcA = (const char*)g_at + (size_t)r0*(EE/2)*4;
    const char* srcB = (const char*)g_wo + (size_t)e0*(EE/2)*4;

    // prefetch chunk 0 into stage 0
    {
        uint32_t base = smb;
        #pragma unroll
        for (int t = 0; t < 4; ++t) {
            int row = r8 + 32*t;
            int sc = (seg ^ (row & 7))*16;
            CPA16(base + row*128 + seg*16, srcA + ((size_t)row*(EE/2))*4 + sc);
        }
        #pragma unroll
        for (int t = 0; t < 2; ++t) {
            int row = r8 + 32*t;
            int sc = (seg ^ (row & 7))*16;
            CPA16(base + 16384 + row*128 + seg*16, srcB + ((size_t)row*(EE/2))*4 + sc);
        }
        CPC();
    }

    int u0c = ((2*q) ^ g)*4;
    int u1c = ((2*q + 1) ^ g)*4;
    int ra0 = (wm + g)*32, ra1 = (wm + g + 8)*32;

    float oacc[8][4] = {};

    for (int j = 0; j < 16; ++j) {
        CPW(0);
        __syncthreads();
        if (j + 1 < 16) {
            int kc = (j + 1)*32;
            uint32_t base = smb + ((j + 1) & 1)*OSTG3*4;
            #pragma unroll
            for (int t = 0; t < 4; ++t) {
                int row = r8 + 32*t;
                int sc = (seg ^ (row & 7))*16;
                CPA16(base + row*128 + seg*16, srcA + ((size_t)row*(EE/2) + kc)*4 + sc);
            }
            #pragma unroll
            for (int t = 0; t < 2; ++t) {
                int row = r8 + 32*t;
                int sc = (seg ^ (row & 7))*16;
                CPA16(base + 16384 + row*128 + seg*16, srcB + ((size_t)row*(EE/2) + kc)*4 + sc);
            }
            CPC();
        }

        const uint32_t* As = smo + (j & 1)*OSTG3;
        const uint32_t* Bs = As + 4096;

        uint4 Aa0 = *(const uint4*)&As[ra0 + u0c], Aa1 = *(const uint4*)&As[ra0 + u1c];
        uint4 Ga0 = *(const uint4*)&As[ra1 + u0c], Ga1 = *(const uint4*)&As[ra1 + u1c];

        #pragma unroll
        for (int nb = 0; nb < 8; ++nb) {
            int rb = (8*nb + g)*32;
            uint4 b0 = *(const uint4*)&Bs[rb + u0c];
            uint4 b1 = *(const uint4*)&Bs[rb + u1c];
            mma_f16(oacc[nb], Aa0.x, Ga0.x, Aa0.y, Ga0.y, b0.x, b0.y);
            mma_f16(oacc[nb], Aa0.z, Ga0.z, Aa0.w, Ga0.w, b0.z, b0.w);
            mma_f16(oacc[nb], Aa1.x, Ga1.x, Aa1.y, Ga1.y, b1.x, b1.y);
            mma_f16(oacc[nb], Aa1.z, Ga1.z, Aa1.w, Ga1.w, b1.z, b1.w);
        }
    }

    float* o0 = &out[(size_t)(r0 + wm + g)*EE + e0];
    float* o1 = &out[(size_t)(r0 + wm + g + 8)*EE + e0];
    #pragma unroll
    for (int nb = 0; nb < 8; ++nb) {
        int c = nb*8 + 2*q;
        float b0 = bo[e0 + c], b1 = bo[e0 + c + 1];
        o0[c] = oacc[nb][0] + b0; o0[c+1] = oacc[nb][1] + b1;
        o1[c] = oacc[nb][2] + b0; o1[c+1] = oacc[nb][3] + b1;
    }
}

// ---------------------------------------------------------------------------
extern "C" void kernel_launch(void* const* d_in, const int* in_sizes, int n_in,
                              void* d_out, int out_size)
{
    const float* x    = (const float*)d_in[0];
    const float* mask = (const float*)d_in[1];
    const float* Wq   = (const float*)d_in[2];
    const float* bq   = (const float*)d_in[3];
    const float* Wk   = (const float*)d_in[4];
    const float* bk   = (const float*)d_in[5];
    const float* Wv   = (const float*)d_in[6];
    const float* bv   = (const float*)d_in[7];
    const float* Wo   = (const float*)d_in[8];
    const float* bo   = (const float*)d_in[9];
    float* out = (float*)d_out;

    cudaFuncSetAttribute(qkv_wo_kernel, cudaFuncAttributeMaxDynamicSharedMemorySize, QKV_SMEM_BYTES);
    cudaFuncSetAttribute(attn_kernel,   cudaFuncAttributeMaxDynamicSharedMemorySize, ATTN_SMEM_BYTES);
    cudaFuncSetAttribute(out_kernel,    cudaFuncAttributeMaxDynamicSharedMemorySize, OUT_SMEM_BYTES);

    qkv_wo_kernel<<<768, 256, QKV_SMEM_BYTES>>>(x, Wq, bq, Wk, bk, Wv, bv, Wo);
    attn_kernel<<<dim3(BH, SS/128), 256, ATTN_SMEM_BYTES>>>(mask);
    out_kernel<<<dim3(EE/64, (BB*SS)/128), 256, OUT_SMEM_BYTES>>>(bo, out);
}

// round 14
// speedup vs baseline: 3.0658x; 1.0262x over previous
#include <cuda_runtime.h>
#include <cuda_bf16.h>
#include <cuda_fp16.h>
#include <math.h>
#include <cstdint>

#define BB 2
#define SS 2048
#define EE 1024
#define HH 16
#define HD 64
#define BH (BB*HH)
#define SCALE_L2E 0.18033688f   // 0.125 * log2(e); attention uses exp2

// Scratch (16B-aligned)
static __device__ __align__(16) uint32_t g_qb[(size_t)BH*SS*32];      // Q fp16x2, scaled
static __device__ __align__(16) uint32_t g_kb[(size_t)BH*SS*32];      // K fp16x2
static __device__ __align__(16) uint32_t g_vb[(size_t)BH*64*(SS/2)];  // V fp16x2, v-major
static __device__ __align__(16) uint32_t g_at[(size_t)BB*SS*(EE/2)];  // att fp16x2, A-frag layout
static __device__ __align__(16) uint32_t g_wo[(size_t)EE*(EE/2)];     // Wo^T fp16x2, B-frag layout

__device__ __forceinline__ uint32_t f2tf32(float x) {
    uint32_t r; asm("cvt.rna.tf32.f32 %0, %1;" : "=r"(r) : "f"(x)); return r;
}
__device__ __forceinline__ float frna(float x) { return __uint_as_float(f2tf32(x)); }
__device__ __forceinline__ uint32_t pack_h2(float a, float b) {
    __half2 h = __floats2half2_rn(a, b);
    return *reinterpret_cast<uint32_t*>(&h);
}
// pack (lo, hi) floats into f16x2 with one CVT
__device__ __forceinline__ uint32_t cvt2_h2(float lo, float hi) {
    uint32_t r; asm("cvt.rn.f16x2.f32 %0, %1, %2;" : "=r"(r) : "f"(hi), "f"(lo)); return r;
}
// two exps in one MUFU op
__device__ __forceinline__ uint32_t ex2_h2(uint32_t x) {
    uint32_t r; asm("ex2.approx.f16x2 %0, %1;" : "=r"(r) : "r"(x)); return r;
}
__device__ __forceinline__ float2 h22f2(uint32_t h) {
    __half2 hh = *reinterpret_cast<__half2*>(&h);
    return __half22float2(hh);
}
__device__ __forceinline__ uint32_t smem_u32(const void* p) {
    uint32_t a;
    asm("{ .reg .u64 t; cvta.to.shared.u64 t, %1; cvt.u32.u64 %0, t; }" : "=r"(a) : "l"(p));
    return a;
}
#define CPA16(d, s) asm volatile("cp.async.ca.shared.global [%0], [%1], 16;" :: "r"(d), "l"(s) : "memory")
#define CPC()       asm volatile("cp.async.commit_group;" ::: "memory")
#define CPW(n)      asm volatile("cp.async.wait_group %0;" :: "n"(n) : "memory")

__device__ __forceinline__ void mma_tf32(float c[4], float a0, float a1, float a2, float a3,
                                         float b0, float b1) {
    asm volatile("mma.sync.aligned.m16n8k8.row.col.f32.tf32.tf32.f32 "
        "{%0,%1,%2,%3}, {%4,%5,%6,%7}, {%8,%9}, {%0,%1,%2,%3};"
        : "+f"(c[0]), "+f"(c[1]), "+f"(c[2]), "+f"(c[3])
        : "r"(__float_as_uint(a0)), "r"(__float_as_uint(a1)),
          "r"(__float_as_uint(a2)), "r"(__float_as_uint(a3)),
          "r"(__float_as_uint(b0)), "r"(__float_as_uint(b1)));
}
__device__ __forceinline__ void mma_f16(float c[4], uint32_t a0, uint32_t a1, uint32_t a2,
                                        uint32_t a3, uint32_t b0, uint32_t b1) {
    asm volatile("mma.sync.aligned.m16n8k16.row.col.f32.f16.f16.f32 "
        "{%0,%1,%2,%3}, {%4,%5,%6,%7}, {%8,%9}, {%0,%1,%2,%3};"
        : "+f"(c[0]), "+f"(c[1]), "+f"(c[2]), "+f"(c[3])
        : "r"(a0), "r"(a1), "r"(a2), "r"(a3), "r"(b0), "r"(b1));
}

// ---------------------------------------------------------------------------
// Kernel 1 (fused): blocks [0,512) = QKV projection (fp16 pack);
//                   blocks [512,768) = Wo pack (fp16, B-frag layout).
// ---------------------------------------------------------------------------
#define QKV_SMEM_BYTES ((128*68 + 3*64*72)*4)

__global__ __launch_bounds__(256, 2) void qkv_wo_kernel(
    const float* __restrict__ x,
    const float* __restrict__ Wq, const float* __restrict__ bq,
    const float* __restrict__ Wk, const float* __restrict__ bk,
    const float* __restrict__ Wv, const float* __restrict__ bv,
    const float* __restrict__ Wo)
{
    extern __shared__ __align__(16) float smf[];
    int tid = threadIdx.x;
    int blk = blockIdx.x;

    if (blk >= 512) {   // ---- Wo pack (fp16 single) ----
        int wid = blk - 512;
        int k0 = (wid & 15)*64, n0 = (wid >> 4)*64;
        float (*t)[65] = (float(*)[65])smf;
        for (int idx = tid; idx < 4096; idx += 256) {
            int ki = idx >> 6, n = idx & 63;
            t[ki][n] = Wo[(size_t)(k0 + ki)*EE + n0 + n];
        }
        __syncthreads();
        int nl = tid >> 2, qq = tid & 3;
        uint32_t hv[8];
        #pragma unroll
        for (int j = 0; j < 8; ++j) {
            int pr = 4*j + qq;
            hv[j] = pack_h2(t[2*pr][nl], t[2*pr + 1][nl]);
        }
        size_t ob = (size_t)(n0 + nl)*(EE/2) + (k0 >> 6)*32 + qq*8;
        *(uint4*)&g_wo[ob]     = make_uint4(hv[0], hv[1], hv[2], hv[3]);
        *(uint4*)&g_wo[ob + 4] = make_uint4(hv[4], hv[5], hv[6], hv[7]);
        return;
    }

    // ---- QKV ----
    float* At = smf;
    float* Ws = smf + 128*68;
    float* Vt = smf + 128*68;     // overlay after Ws reads done

    int lane = tid & 31, warp = tid >> 5;
    int g = lane >> 2, q = lane & 3;
    int bh = blk & 31, b = bh >> 4, h = bh & 15;
    int s0 = (blk >> 5) * 128, wm = warp * 16;

    for (int idx = tid; idx < 2048; idx += 256) {
        int row = idx >> 4, c4 = (idx & 15)*4;
        *(float4*)&At[row*68 + c4] = *(const float4*)&x[((size_t)b*SS + s0 + row)*EE + h*HD + c4];
    }
    const float* Wp[3] = {Wq, Wk, Wv};
    for (int w = 0; w < 3; ++w)
        for (int idx = tid; idx < 1024; idx += 256) {
            int row = idx >> 4, c4 = (idx & 15)*4;
            *(float4*)&Ws[w*64*72 + row*72 + c4] = *(const float4*)&Wp[w][(size_t)row*64 + c4];
        }
    __syncthreads();

    int r0g = s0 + wm + g, r1g = s0 + wm + g + 8;
    const float* bp[3] = {bq, bk, bv};

    for (int w = 0; w < 3; ++w) {
        float acc[8][4] = {};
        const float* B = &Ws[w*64*72];
        #pragma unroll
        for (int kk = 0; kk < 8; ++kk) {
            float a0 = frna(At[(wm + g)*68 + kk*8 + q]);
            float a1 = frna(At[(wm + g + 8)*68 + kk*8 + q]);
            float a2 = frna(At[(wm + g)*68 + kk*8 + q + 4]);
            float a3 = frna(At[(wm + g + 8)*68 + kk*8 + q + 4]);
            #pragma unroll
            for (int nb = 0; nb < 8; ++nb) {
                float b0 = frna(B[(kk*8 + q)*72 + nb*8 + g]);
                float b1 = frna(B[(kk*8 + q + 4)*72 + nb*8 + g]);
                mma_tf32(acc[nb], a0, a1, a2, a3, b0, b1);
            }
        }

        if (w == 0) {
            #pragma unroll
            for (int nb = 0; nb < 8; ++nb) {
                int c = nb*8 + 2*q;
                float b0 = bp[0][c], b1 = bp[0][c+1];
                g_qb[((size_t)bh*SS + r0g)*32 + q*8 + nb] = pack_h2((acc[nb][0]+b0)*SCALE_L2E, (acc[nb][1]+b1)*SCALE_L2E);
                g_qb[((size_t)bh*SS + r1g)*32 + q*8 + nb] = pack_h2((acc[nb][2]+b0)*SCALE_L2E, (acc[nb][3]+b1)*SCALE_L2E);
            }
        } else if (w == 1) {
            #pragma unroll
            for (int nb = 0; nb < 8; ++nb) {
                int c = nb*8 + 2*q;
                float b0 = bp[1][c], b1 = bp[1][c+1];
                g_kb[((size_t)bh*SS + r0g)*32 + q*8 + nb] = pack_h2(acc[nb][0]+b0, acc[nb][1]+b1);
                g_kb[((size_t)bh*SS + r1g)*32 + q*8 + nb] = pack_h2(acc[nb][2]+b0, acc[nb][3]+b1);
            }
        } else {
            __syncthreads();
            int rl0 = wm + g, rl1 = wm + g + 8;
            #pragma unroll
            for (int nb = 0; nb < 8; ++nb) {
                int c = nb*8 + 2*q;
                float b0 = bp[2][c], b1 = bp[2][c+1];
                Vt[rl0*65 + c] = acc[nb][0]+b0; Vt[rl0*65 + c+1] = acc[nb][1]+b1;
                Vt[rl1*65 + c] = acc[nb][2]+b0; Vt[rl1*65 + c+1] = acc[nb][3]+b1;
            }
            __syncthreads();
            int v = tid & 63, idx2 = tid >> 6, tl = idx2 >> 1, half = idx2 & 1;
            uint32_t hv[16];
            #pragma unroll
            for (int j = 0; j < 16; ++j) {
                int pos = half*16 + j;
                int qv = pos >> 3, kk = (pos & 7) >> 1, hh = pos & 1;
                int sl = tl*64 + 2*(8*kk + 4*hh + qv);
                hv[j] = pack_h2(Vt[sl*65 + v], Vt[(sl+1)*65 + v]);
            }
            size_t ob = ((size_t)bh*64 + v)*(SS/2) + (s0 >> 1) + tl*32 + half*16;
            #pragma unroll
            for (int u = 0; u < 4; ++u)
                *(uint4*)&g_vb[ob + 4*u] = make_uint4(hv[4*u], hv[4*u+1], hv[4*u+2], hv[4*u+3]);
        }
    }
}

// ---------------------------------------------------------------------------
// Kernel 2: attention, fp16 mma, ex2.approx.f16x2 softmax, cp.async 3-stage.
// ---------------------------------------------------------------------------
#define SSTG (2*64*32)                  // 4096 u32 = 16KB
#define ATTN_SMEM_BYTES (3*SSTG*4)      // 49152

__global__ __launch_bounds__(256, 2) void attn_kernel(const float* __restrict__ mask)
{
    extern __shared__ __align__(16) uint32_t smu[];
    uint32_t smb = smem_u32(smu);

    int tid = threadIdx.x, lane = tid & 31, warp = tid >> 5;
    int g = lane >> 2, q = lane & 3;
    int bh = blockIdx.x, b = bh >> 4, h = bh & 15;
    int q0 = blockIdx.y * 128, wr = q0 + warp*16;

    int r8 = tid >> 3, seg = tid & 7;
    const char* srcK = (const char*)g_kb + ((size_t)bh*SS)*128;
    const char* srcV = (const char*)g_vb + ((size_t)bh*64)*(SS/2)*4;

    #pragma unroll
    for (int pf = 0; pf < 2; ++pf) {
        int s0 = pf*64;
        uint32_t base = smb + (pf % 3)*SSTG*4;
        #pragma unroll
        for (int t = 0; t < 2; ++t) {
            int row = r8 + 32*t;
            int sc = (seg ^ (row & 7))*16;
            uint32_t doff = row*128 + seg*16;
            CPA16(base + doff,        srcK + (size_t)(s0+row)*128 + sc);
            CPA16(base + 8192 + doff, srcV + ((size_t)row*(SS/2) + (s0>>1))*4 + sc);
        }
        CPC();
    }

    uint32_t qa[8], qg[8];
    {
        const uint4* p0 = (const uint4*)&g_qb[((size_t)bh*SS + wr + g)*32 + q*8];
        const uint4* p1 = (const uint4*)&g_qb[((size_t)bh*SS + wr + g + 8)*32 + q*8];
        uint4 u0 = p0[0], u1 = p0[1], v0 = p1[0], v1 = p1[1];
        qa[0]=u0.x; qa[1]=u0.y; qa[2]=u0.z; qa[3]=u0.w; qa[4]=u1.x; qa[5]=u1.y; qa[6]=u1.z; qa[7]=u1.w;
        qg[0]=v0.x; qg[1]=v0.y; qg[2]=v0.z; qg[3]=v0.w; qg[4]=v1.x; qg[5]=v1.y; qg[6]=v1.z; qg[7]=v1.w;
    }

    float oacc[8][4] = {};
    float lsum0 = 0.f, lsum1 = 0.f;
    const float* mrow0 = &mask[(size_t)(wr + g)*SS];
    const float* mrow1 = &mask[(size_t)(wr + g + 8)*SS];
    int u0c = ((2*q) ^ g)*4;
    int u1c = ((2*q + 1) ^ g)*4;

    for (int jt = 0; jt < 32; ++jt) {
        if (jt < 31) { CPW(1); } else { CPW(0); }
        __syncthreads();
        if (jt + 2 < 32) {
            int s0n = (jt+2)*64;
            uint32_t base = smb + ((jt+2) % 3)*SSTG*4;
            #pragma unroll
            for (int t = 0; t < 2; ++t) {
                int row = r8 + 32*t;
                int sc = (seg ^ (row & 7))*16;
                uint32_t doff = row*128 + seg*16;
                CPA16(base + doff,        srcK + (size_t)(s0n+row)*128 + sc);
                CPA16(base + 8192 + doff, srcV + ((size_t)row*(SS/2) + (s0n>>1))*4 + sc);
            }
            CPC();
        }

        const uint32_t* Kb = smu + (jt % 3)*SSTG;
        const uint32_t* Vs = Kb + 2048;
        int s0 = jt*64;

        // S = Q K^T
        float sacc[8][4] = {};
        #pragma unroll
        for (int nb = 0; nb < 8; ++nb) {
            int rb = (8*nb + g)*32;
            uint4 k0 = *(const uint4*)&Kb[rb + u0c];
            uint4 k1 = *(const uint4*)&Kb[rb + u1c];
            mma_f16(sacc[nb], qa[0], qg[0], qa[1], qg[1], k0.x, k0.y);
            mma_f16(sacc[nb], qa[2], qg[2], qa[3], qg[3], k0.z, k0.w);
            mma_f16(sacc[nb], qa[4], qg[4], qa[5], qg[5], k1.x, k1.y);
            mma_f16(sacc[nb], qa[6], qg[6], qa[7], qg[7], k1.z, k1.w);
        }

        // P = exp2(S * mask) via ex2.approx.f16x2 (one MUFU op per pair)
        uint32_t ph[8], pg[8];
        float ps0 = 0.f, ps1 = 0.f;
        #pragma unroll
        for (int nb = 0; nb < 8; ++nb) {
            float2 m0 = __ldg((const float2*)&mrow0[s0 + 8*nb + 2*q]);
            float2 m1 = __ldg((const float2*)&mrow1[s0 + 8*nb + 2*q]);
            uint32_t x01 = cvt2_h2(sacc[nb][0]*m0.x, sacc[nb][1]*m0.y);
            uint32_t x23 = cvt2_h2(sacc[nb][2]*m1.x, sacc[nb][3]*m1.y);
            ph[nb] = ex2_h2(x01);
            pg[nb] = ex2_h2(x23);
            float2 f0 = h22f2(ph[nb]);
            float2 f1 = h22f2(pg[nb]);
            ps0 += f0.x + f0.y;
            ps1 += f1.x + f1.y;
        }
        ps0 += __shfl_xor_sync(0xffffffffu, ps0, 1);
        ps0 += __shfl_xor_sync(0xffffffffu, ps0, 2);
        ps1 += __shfl_xor_sync(0xffffffffu, ps1, 1);
        ps1 += __shfl_xor_sync(0xffffffffu, ps1, 2);
        lsum0 += ps0; lsum1 += ps1;

        // O += P V
        #pragma unroll
        for (int nb = 0; nb < 8; ++nb) {
            int rb = (8*nb + g)*32;
            uint4 v0 = *(const uint4*)&Vs[rb + u0c];
            uint4 v1 = *(const uint4*)&Vs[rb + u1c];
            mma_f16(oacc[nb], ph[0], pg[0], ph[1], pg[1], v0.x, v0.y);
            mma_f16(oacc[nb], ph[2], pg[2], ph[3], pg[3], v0.z, v0.w);
            mma_f16(oacc[nb], ph[4], pg[4], ph[5], pg[5], v1.x, v1.y);
            mma_f16(oacc[nb], ph[6], pg[6], ph[7], pg[7], v1.z, v1.w);
        }
    }

    // epilogue: normalize, pack fp16, write in A-fragment layout (pos q*8+nb)
    float inv0 = 1.f/lsum0, inv1 = 1.f/lsum1;
    size_t base0 = ((size_t)b*SS + wr + g)*(EE/2) + h*32;
    size_t base1 = ((size_t)b*SS + wr + g + 8)*(EE/2) + h*32;
    #pragma unroll
    for (int nb = 0; nb < 8; ++nb) {
        int pos = q*8 + nb;
        g_at[base0 + pos] = pack_h2(oacc[nb][0]*inv0, oacc[nb][1]*inv0);
        g_at[base1 + pos] = pack_h2(oacc[nb][2]*inv1, oacc[nb][3]*inv1);
    }
}

// ---------------------------------------------------------------------------
// Kernel 3: output projection, fp16 single-term; A and B via cp.async 2-stage.
// ---------------------------------------------------------------------------
#define OSTG3 6144
#define OUT_SMEM_BYTES (2*OSTG3*4)      // 49152

__global__ __launch_bounds__(256, 2) void out_kernel(
    const float* __restrict__ bo, float* __restrict__ out)
{
    extern __shared__ __align__(16) uint32_t smo[];
    uint32_t smb = smem_u32(smo);

    int tid = threadIdx.x, lane = tid & 31, warp = tid >> 5;
    int g = lane >> 2, q = lane & 3;
    int e0 = blockIdx.x*64, r0 = blockIdx.y*128, wm = warp*16;

    int r8 = tid >> 3, seg = tid & 7;
    const char* srcA = (const char*)g_at + (size_t)r0*(EE/2)*4;
    const char* srcB = (const char*)g_wo + (size_t)e0*(EE/2)*4;

    {
        uint32_t base = smb;
        #pragma unroll
        for (int t = 0; t < 4; ++t) {
            int row = r8 + 32*t;
            int sc = (seg ^ (row & 7))*16;
            CPA16(base + row*128 + seg*16, srcA + ((size_t)row*(EE/2))*4 + sc);
        }
        #pragma unroll
        for (int t = 0; t < 2; ++t) {
            int row = r8 + 32*t;
            int sc = (seg ^ (row & 7))*16;
            CPA16(base + 16384 + row*128 + seg*16, srcB + ((size_t)row*(EE/2))*4 + sc);
        }
        CPC();
    }

    int u0c = ((2*q) ^ g)*4;
    int u1c = ((2*q + 1) ^ g)*4;
    int ra0 = (wm + g)*32, ra1 = (wm + g + 8)*32;

    float oacc[8][4] = {};

    for (int j = 0; j < 16; ++j) {
        CPW(0);
        __syncthreads();
        if (j + 1 < 16) {
            int kc = (j + 1)*32;
            uint32_t base = smb + ((j + 1) & 1)*OSTG3*4;
            #pragma unroll
            for (int t = 0; t < 4; ++t) {
                int row = r8 + 32*t;
                int sc = (seg ^ (row & 7))*16;
                CPA16(base + row*128 + seg*16, srcA + ((size_t)row*(EE/2) + kc)*4 + sc);
            }
            #pragma unroll
            for (int t = 0; t < 2; ++t) {
                int row = r8 + 32*t;
                int sc = (seg ^ (row & 7))*16;
                CPA16(base + 16384 + row*128 + seg*16, srcB + ((size_t)row*(EE/2) + kc)*4 + sc);
            }
            CPC();
        }

        const uint32_t* As = smo + (j & 1)*OSTG3;
        const uint32_t* Bs = As + 4096;

        uint4 Aa0 = *(const uint4*)&As[ra0 + u0c], Aa1 = *(const uint4*)&As[ra0 + u1c];
        uint4 Ga0 = *(const uint4*)&As[ra1 + u0c], Ga1 = *(const uint4*)&As[ra1 + u1c];

        #pragma unroll
        for (int nb = 0; nb < 8; ++nb) {
            int rb = (8*nb + g)*32;
            uint4 b0 = *(const uint4*)&Bs[rb + u0c];
            uint4 b1 = *(const uint4*)&Bs[rb + u1c];
            mma_f16(oacc[nb], Aa0.x, Ga0.x, Aa0.y, Ga0.y, b0.x, b0.y);
            mma_f16(oacc[nb], Aa0.z, Ga0.z, Aa0.w, Ga0.w, b0.z, b0.w);
            mma_f16(oacc[nb], Aa1.x, Ga1.x, Aa1.y, Ga1.y, b1.x, b1.y);
            mma_f16(oacc[nb], Aa1.z, Ga1.z, Aa1.w, Ga1.w, b1.z, b1.w);
        }
    }

    float* o0 = &out[(size_t)(r0 + wm + g)*EE + e0];
    float* o1 = &out[(size_t)(r0 + wm + g + 8)*EE + e0];
    #pragma unroll
    for (int nb = 0; nb < 8; ++nb) {
        int c = nb*8 + 2*q;
        float b0 = bo[e0 + c], b1 = bo[e0 + c + 1];
        o0[c] = oacc[nb][0] + b0; o0[c+1] = oacc[nb][1] + b1;
        o1[c] = oacc[nb][2] + b0; o1[c+1] = oacc[nb][3] + b1;
    }
}

// ---------------------------------------------------------------------------
extern "C" void kernel_launch(void* const* d_in, const int* in_sizes, int n_in,
                              void* d_out, int out_size)
{
    const float* x    = (const float*)d_in[0];
    const float* mask = (const float*)d_in[1];
    const float* Wq   = (const float*)d_in[2];
    const float* bq   = (const float*)d_in[3];
    const float* Wk   = (const float*)d_in[4];
    const float* bk   = (const float*)d_in[5];
    const float* Wv   = (const float*)d_in[6];
    const float* bv   = (const float*)d_in[7];
    const float* Wo   = (const float*)d_in[8];
    const float* bo   = (const float*)d_in[9];
    float* out = (float*)d_out;

    cudaFuncSetAttribute(qkv_wo_kernel, cudaFuncAttributeMaxDynamicSharedMemorySize, QKV_SMEM_BYTES);
    cudaFuncSetAttribute(attn_kernel,   cudaFuncAttributeMaxDynamicSharedMemorySize, ATTN_SMEM_BYTES);
    cudaFuncSetAttribute(out_kernel,    cudaFuncAttributeMaxDynamicSharedMemorySize, OUT_SMEM_BYTES);

    qkv_wo_kernel<<<768, 256, QKV_SMEM_BYTES>>>(x, Wq, bq, Wk, bk, Wv, bv, Wo);
    attn_kernel<<<dim3(BH, SS/128), 256, ATTN_SMEM_BYTES>>>(mask);
    out_kernel<<<dim3(EE/64, (BB*SS)/128), 256, OUT_SMEM_BYTES>>>(bo, out);
}

// round 15
// speedup vs baseline: 3.1033x; 1.0122x over previous
#include <cuda_runtime.h>
#include <cuda_bf16.h>
#include <cuda_fp16.h>
#include <math.h>
#include <cstdint>

#define BB 2
#define SS 2048
#define EE 1024
#define HH 16
#define HD 64
#define BH (BB*HH)
#define SCALE_L2E 0.18033688f   // 0.125 * log2(e); attention uses exp2

// Scratch (16B-aligned)
static __device__ __align__(16) uint32_t g_qb[(size_t)BH*SS*32];      // Q fp16x2, scaled
static __device__ __align__(16) uint32_t g_kb[(size_t)BH*SS*32];      // K fp16x2
static __device__ __align__(16) uint32_t g_vb[(size_t)BH*64*(SS/2)];  // V fp16x2, v-major
static __device__ __align__(16) uint32_t g_at[(size_t)BB*SS*(EE/2)];  // att fp16x2, A-frag layout
static __device__ __align__(16) uint32_t g_wo[(size_t)EE*(EE/2)];     // Wo^T fp16x2, B-frag layout

__device__ __forceinline__ uint32_t pack_h2(float a, float b) {
    __half2 h = __floats2half2_rn(a, b);
    return *reinterpret_cast<uint32_t*>(&h);
}
__device__ __forceinline__ uint32_t cvt2_h2(float lo, float hi) {
    uint32_t r; asm("cvt.rn.f16x2.f32 %0, %1, %2;" : "=r"(r) : "f"(hi), "f"(lo)); return r;
}
__device__ __forceinline__ uint32_t ex2_h2(uint32_t x) {
    uint32_t r; asm("ex2.approx.f16x2 %0, %1;" : "=r"(r) : "r"(x)); return r;
}
__device__ __forceinline__ float2 h22f2(uint32_t h) {
    __half2 hh = *reinterpret_cast<__half2*>(&h);
    return __half22float2(hh);
}
__device__ __forceinline__ uint32_t smem_u32(const void* p) {
    uint32_t a;
    asm("{ .reg .u64 t; cvta.to.shared.u64 t, %1; cvt.u32.u64 %0, t; }" : "=r"(a) : "l"(p));
    return a;
}
#define CPA16(d, s) asm volatile("cp.async.ca.shared.global [%0], [%1], 16;" :: "r"(d), "l"(s) : "memory")
#define CPC()       asm volatile("cp.async.commit_group;" ::: "memory")
#define CPW(n)      asm volatile("cp.async.wait_group %0;" :: "n"(n) : "memory")

__device__ __forceinline__ void mma_f16(float c[4], uint32_t a0, uint32_t a1, uint32_t a2,
                                        uint32_t a3, uint32_t b0, uint32_t b1) {
    asm volatile("mma.sync.aligned.m16n8k16.row.col.f32.f16.f16.f32 "
        "{%0,%1,%2,%3}, {%4,%5,%6,%7}, {%8,%9}, {%0,%1,%2,%3};"
        : "+f"(c[0]), "+f"(c[1]), "+f"(c[2]), "+f"(c[3])
        : "r"(a0), "r"(a1), "r"(a2), "r"(a3), "r"(b0), "r"(b1));
}

// ---------------------------------------------------------------------------
// Kernel 1 (fused): blocks [0,512) = QKV projection (fp16 mma);
//                   blocks [512,768) = Wo pack (fp16, B-frag layout).
// smem (bytes): At16 u32 [0,16384) | Wsf f32 [16384,33792) | Bs u32 [33792,41984)
// Vt f32 [0,33280) overlays At16+Wsf during the V epilogue.
// ---------------------------------------------------------------------------
#define QKV_SMEM_BYTES 41984

__global__ __launch_bounds__(256, 3) void qkv_wo_kernel(
    const float* __restrict__ x,
    const float* __restrict__ Wq, const float* __restrict__ bq,
    const float* __restrict__ Wk, const float* __restrict__ bk,
    const float* __restrict__ Wv, const float* __restrict__ bv,
    const float* __restrict__ Wo)
{
    extern __shared__ __align__(16) uint32_t smq[];
    int tid = threadIdx.x;
    int blk = blockIdx.x;

    if (blk >= 512) {   // ---- Wo pack (fp16, B-frag layout) ----
        float (*t)[65] = (float(*)[65])smq;
        int wid = blk - 512;
        int k0 = (wid & 15)*64, n0 = (wid >> 4)*64;
        for (int idx = tid; idx < 4096; idx += 256) {
            int ki = idx >> 6, n = idx & 63;
            t[ki][n] = Wo[(size_t)(k0 + ki)*EE + n0 + n];
        }
        __syncthreads();
        int nl = tid >> 2, qq = tid & 3;
        uint32_t hv[8];
        #pragma unroll
        for (int j = 0; j < 8; ++j) {
            int pr = 4*j + qq;
            hv[j] = pack_h2(t[2*pr][nl], t[2*pr + 1][nl]);
        }
        size_t ob = (size_t)(n0 + nl)*(EE/2) + (k0 >> 6)*32 + qq*8;
        *(uint4*)&g_wo[ob]     = make_uint4(hv[0], hv[1], hv[2], hv[3]);
        *(uint4*)&g_wo[ob + 4] = make_uint4(hv[4], hv[5], hv[6], hv[7]);
        return;
    }

    // ---- QKV (fp16 mma) ----
    uint32_t* At16 = smq;                     // [128 m][32 pos], XOR-swizzled
    float*    Wsf  = (float*)(smq + 4096);    // [64 k][n] stride 68
    uint32_t* Bs   = smq + 8448;              // [64 n][32 pos], XOR-swizzled
    float*    Vt   = (float*)smq;             // overlay: [128 s][64 v] stride 65

    int lane = tid & 31, warp = tid >> 5;
    int g = lane >> 2, q = lane & 3;
    int bh = blk & 31, b = bh >> 4, h = bh & 15;
    int s0 = (blk >> 5) * 128, wm = warp * 16;

    // stage x -> fp16 A-frag layout. pos p: chunk XOR-swizzled with row&7.
    for (int idx = tid; idx < 2048; idx += 256) {
        int row = idx >> 4, i = idx & 15;
        float4 v = *(const float4*)&x[((size_t)b*SS + s0 + row)*EE + h*HD + i*4];
        int p0 = ((2*i) & 3)*8 + (i >> 1);
        int p1 = ((2*i + 1) & 3)*8 + (i >> 1);
        int sw0 = ((p0 >> 2) ^ (row & 7))*4 + (p0 & 3);
        int sw1 = ((p1 >> 2) ^ (row & 7))*4 + (p1 & 3);
        At16[row*32 + sw0] = pack_h2(v.x, v.y);
        At16[row*32 + sw1] = pack_h2(v.z, v.w);
    }
    __syncthreads();

    // A fragments: load once, reuse for all three W
    int u0c = ((2*q) ^ g)*4;
    int u1c = ((2*q + 1) ^ g)*4;
    uint32_t qa[8], qg[8];
    {
        int ra0 = (wm + g)*32, ra1 = (wm + g + 8)*32;
        uint4 a0 = *(const uint4*)&At16[ra0 + u0c], a1 = *(const uint4*)&At16[ra0 + u1c];
        uint4 c0 = *(const uint4*)&At16[ra1 + u0c], c1 = *(const uint4*)&At16[ra1 + u1c];
        qa[0]=a0.x; qa[1]=a0.y; qa[2]=a0.z; qa[3]=a0.w; qa[4]=a1.x; qa[5]=a1.y; qa[6]=a1.z; qa[7]=a1.w;
        qg[0]=c0.x; qg[1]=c0.y; qg[2]=c0.z; qg[3]=c0.w; qg[4]=c1.x; qg[5]=c1.y; qg[6]=c1.z; qg[7]=c1.w;
    }

    int r0g = s0 + wm + g, r1g = s0 + wm + g + 8;
    const float* Wp[3] = {Wq, Wk, Wv};
    const float* bp[3] = {bq, bk, bv};

    for (int w = 0; w < 3; ++w) {
        // load W (fp32, coalesced), then pack to fp16 B-frag layout
        for (int idx = tid; idx < 1024; idx += 256) {
            int row = idx >> 4, c4 = (idx & 15)*4;
            *(float4*)&Wsf[row*68 + c4] = *(const float4*)&Wp[w][(size_t)row*64 + c4];
        }
        __syncthreads();
        {
            int n = tid >> 2, qq = tid & 3;
            #pragma unroll
            for (int j = 0; j < 8; ++j) {
                int c = 8*j + 2*qq;
                int p = qq*8 + j;
                int sw = ((p >> 2) ^ (n & 7))*4 + (p & 3);
                Bs[n*32 + sw] = pack_h2(Wsf[c*68 + n], Wsf[(c + 1)*68 + n]);
            }
        }
        __syncthreads();

        float acc[8][4] = {};
        #pragma unroll
        for (int nb = 0; nb < 8; ++nb) {
            int rb = (8*nb + g)*32;
            uint4 b0 = *(const uint4*)&Bs[rb + u0c];
            uint4 b1 = *(const uint4*)&Bs[rb + u1c];
            mma_f16(acc[nb], qa[0], qg[0], qa[1], qg[1], b0.x, b0.y);
            mma_f16(acc[nb], qa[2], qg[2], qa[3], qg[3], b0.z, b0.w);
            mma_f16(acc[nb], qa[4], qg[4], qa[5], qg[5], b1.x, b1.y);
            mma_f16(acc[nb], qa[6], qg[6], qa[7], qg[7], b1.z, b1.w);
        }

        if (w == 0) {
            #pragma unroll
            for (int nb = 0; nb < 8; ++nb) {
                int c = nb*8 + 2*q;
                float b0 = bp[0][c], b1 = bp[0][c+1];
                g_qb[((size_t)bh*SS + r0g)*32 + q*8 + nb] = pack_h2((acc[nb][0]+b0)*SCALE_L2E, (acc[nb][1]+b1)*SCALE_L2E);
                g_qb[((size_t)bh*SS + r1g)*32 + q*8 + nb] = pack_h2((acc[nb][2]+b0)*SCALE_L2E, (acc[nb][3]+b1)*SCALE_L2E);
            }
            __syncthreads();   // Bs reads done before next w reloads Wsf
        } else if (w == 1) {
            #pragma unroll
            for (int nb = 0; nb < 8; ++nb) {
                int c = nb*8 + 2*q;
                float b0 = bp[1][c], b1 = bp[1][c+1];
                g_kb[((size_t)bh*SS + r0g)*32 + q*8 + nb] = pack_h2(acc[nb][0]+b0, acc[nb][1]+b1);
                g_kb[((size_t)bh*SS + r1g)*32 + q*8 + nb] = pack_h2(acc[nb][2]+b0, acc[nb][3]+b1);
            }
            __syncthreads();
        } else {
            // V: stage fp32 into Vt (overlays At16+Wsf; both dead), then repack
            __syncthreads();   // everyone done with At16/Bs mma reads
            int rl0 = wm + g, rl1 = wm + g + 8;
            #pragma unroll
            for (int nb = 0; nb < 8; ++nb) {
                int c = nb*8 + 2*q;
                float b0 = bp[2][c], b1 = bp[2][c+1];
                Vt[rl0*65 + c] = acc[nb][0]+b0; Vt[rl0*65 + c+1] = acc[nb][1]+b1;
                Vt[rl1*65 + c] = acc[nb][2]+b0; Vt[rl1*65 + c+1] = acc[nb][3]+b1;
            }
            __syncthreads();
            int v = tid & 63, idx2 = tid >> 6, tl = idx2 >> 1, half = idx2 & 1;
            uint32_t hv[16];
            #pragma unroll
            for (int j = 0; j < 16; ++j) {
                int pos = half*16 + j;
                int qv = pos >> 3, kk = (pos & 7) >> 1, hh = pos & 1;
                int sl = tl*64 + 2*(8*kk + 4*hh + qv);
                hv[j] = pack_h2(Vt[sl*65 + v], Vt[(sl+1)*65 + v]);
            }
            size_t ob = ((size_t)bh*64 + v)*(SS/2) + (s0 >> 1) + tl*32 + half*16;
            #pragma unroll
            for (int u = 0; u < 4; ++u)
                *(uint4*)&g_vb[ob + 4*u] = make_uint4(hv[4*u], hv[4*u+1], hv[4*u+2], hv[4*u+3]);
        }
    }
}

// ---------------------------------------------------------------------------
// Kernel 2: attention, fp16 mma, ex2.approx.f16x2 softmax, cp.async 3-stage.
// ---------------------------------------------------------------------------
#define SSTG (2*64*32)                  // 4096 u32 = 16KB
#define ATTN_SMEM_BYTES (3*SSTG*4)      // 49152

__global__ __launch_bounds__(256, 2) void attn_kernel(const float* __restrict__ mask)
{
    extern __shared__ __align__(16) uint32_t smu[];
    uint32_t smb = smem_u32(smu);

    int tid = threadIdx.x, lane = tid & 31, warp = tid >> 5;
    int g = lane >> 2, q = lane & 3;
    int bh = blockIdx.x, b = bh >> 4, h = bh & 15;
    int q0 = blockIdx.y * 128, wr = q0 + warp*16;

    int r8 = tid >> 3, seg = tid & 7;
    const char* srcK = (const char*)g_kb + ((size_t)bh*SS)*128;
    const char* srcV = (const char*)g_vb + ((size_t)bh*64)*(SS/2)*4;

    #pragma unroll
    for (int pf = 0; pf < 2; ++pf) {
        int s0 = pf*64;
        uint32_t base = smb + (pf % 3)*SSTG*4;
        #pragma unroll
        for (int t = 0; t < 2; ++t) {
            int row = r8 + 32*t;
            int sc = (seg ^ (row & 7))*16;
            uint32_t doff = row*128 + seg*16;
            CPA16(base + doff,        srcK + (size_t)(s0+row)*128 + sc);
            CPA16(base + 8192 + doff, srcV + ((size_t)row*(SS/2) + (s0>>1))*4 + sc);
        }
        CPC();
    }

    uint32_t qa[8], qg[8];
    {
        const uint4* p0 = (const uint4*)&g_qb[((size_t)bh*SS + wr + g)*32 + q*8];
        const uint4* p1 = (const uint4*)&g_qb[((size_t)bh*SS + wr + g + 8)*32 + q*8];
        uint4 u0 = p0[0], u1 = p0[1], v0 = p1[0], v1 = p1[1];
        qa[0]=u0.x; qa[1]=u0.y; qa[2]=u0.z; qa[3]=u0.w; qa[4]=u1.x; qa[5]=u1.y; qa[6]=u1.z; qa[7]=u1.w;
        qg[0]=v0.x; qg[1]=v0.y; qg[2]=v0.z; qg[3]=v0.w; qg[4]=v1.x; qg[5]=v1.y; qg[6]=v1.z; qg[7]=v1.w;
    }

    float oacc[8][4] = {};
    float lsum0 = 0.f, lsum1 = 0.f;
    const float* mrow0 = &mask[(size_t)(wr + g)*SS];
    const float* mrow1 = &mask[(size_t)(wr + g + 8)*SS];
    int u0c = ((2*q) ^ g)*4;
    int u1c = ((2*q + 1) ^ g)*4;

    for (int jt = 0; jt < 32; ++jt) {
        if (jt < 31) { CPW(1); } else { CPW(0); }
        __syncthreads();
        if (jt + 2 < 32) {
            int s0n = (jt+2)*64;
            uint32_t base = smb + ((jt+2) % 3)*SSTG*4;
            #pragma unroll
            for (int t = 0; t < 2; ++t) {
                int row = r8 + 32*t;
                int sc = (seg ^ (row & 7))*16;
                uint32_t doff = row*128 + seg*16;
                CPA16(base + doff,        srcK + (size_t)(s0n+row)*128 + sc);
                CPA16(base + 8192 + doff, srcV + ((size_t)row*(SS/2) + (s0n>>1))*4 + sc);
            }
            CPC();
        }

        const uint32_t* Kb = smu + (jt % 3)*SSTG;
        const uint32_t* Vs = Kb + 2048;
        int s0 = jt*64;

        // S = Q K^T
        float sacc[8][4] = {};
        #pragma unroll
        for (int nb = 0; nb < 8; ++nb) {
            int rb = (8*nb + g)*32;
            uint4 k0 = *(const uint4*)&Kb[rb + u0c];
            uint4 k1 = *(const uint4*)&Kb[rb + u1c];
            mma_f16(sacc[nb], qa[0], qg[0], qa[1], qg[1], k0.x, k0.y);
            mma_f16(sacc[nb], qa[2], qg[2], qa[3], qg[3], k0.z, k0.w);
            mma_f16(sacc[nb], qa[4], qg[4], qa[5], qg[5], k1.x, k1.y);
            mma_f16(sacc[nb], qa[6], qg[6], qa[7], qg[7], k1.z, k1.w);
        }

        // P = exp2(S * mask) via ex2.approx.f16x2
        uint32_t ph[8], pg[8];
        float ps0 = 0.f, ps1 = 0.f;
        #pragma unroll
        for (int nb = 0; nb < 8; ++nb) {
            float2 m0 = __ldg((const float2*)&mrow0[s0 + 8*nb + 2*q]);
            float2 m1 = __ldg((const float2*)&mrow1[s0 + 8*nb + 2*q]);
            uint32_t x01 = cvt2_h2(sacc[nb][0]*m0.x, sacc[nb][1]*m0.y);
            uint32_t x23 = cvt2_h2(sacc[nb][2]*m1.x, sacc[nb][3]*m1.y);
            ph[nb] = ex2_h2(x01);
            pg[nb] = ex2_h2(x23);
            float2 f0 = h22f2(ph[nb]);
            float2 f1 = h22f2(pg[nb]);
            ps0 += f0.x + f0.y;
            ps1 += f1.x + f1.y;
        }
        ps0 += __shfl_xor_sync(0xffffffffu, ps0, 1);
        ps0 += __shfl_xor_sync(0xffffffffu, ps0, 2);
        ps1 += __shfl_xor_sync(0xffffffffu, ps1, 1);
        ps1 += __shfl_xor_sync(0xffffffffu, ps1, 2);
        lsum0 += ps0; lsum1 += ps1;

        // O += P V
        #pragma unroll
        for (int nb = 0; nb < 8; ++nb) {
            int rb = (8*nb + g)*32;
            uint4 v0 = *(const uint4*)&Vs[rb + u0c];
            uint4 v1 = *(const uint4*)&Vs[rb + u1c];
            mma_f16(oacc[nb], ph[0], pg[0], ph[1], pg[1], v0.x, v0.y);
            mma_f16(oacc[nb], ph[2], pg[2], ph[3], pg[3], v0.z, v0.w);
            mma_f16(oacc[nb], ph[4], pg[4], ph[5], pg[5], v1.x, v1.y);
            mma_f16(oacc[nb], ph[6], pg[6], ph[7], pg[7], v1.z, v1.w);
        }
    }

    // epilogue: normalize, pack fp16, write in A-fragment layout (pos q*8+nb)
    float inv0 = 1.f/lsum0, inv1 = 1.f/lsum1;
    size_t base0 = ((size_t)b*SS + wr + g)*(EE/2) + h*32;
    size_t base1 = ((size_t)b*SS + wr + g + 8)*(EE/2) + h*32;
    #pragma unroll
    for (int nb = 0; nb < 8; ++nb) {
        int pos = q*8 + nb;
        g_at[base0 + pos] = pack_h2(oacc[nb][0]*inv0, oacc[nb][1]*inv0);
        g_at[base1 + pos] = pack_h2(oacc[nb][2]*inv1, oacc[nb][3]*inv1);
    }
}

// ---------------------------------------------------------------------------
// Kernel 3: output projection, fp16 single-term; A and B via cp.async 2-stage.
// ---------------------------------------------------------------------------
#define OSTG3 6144
#define OUT_SMEM_BYTES (2*OSTG3*4)      // 49152

__global__ __launch_bounds__(256, 2) void out_kernel(
    const float* __restrict__ bo, float* __restrict__ out)
{
    extern __shared__ __align__(16) uint32_t smo[];
    uint32_t smb = smem_u32(smo);

    int tid = threadIdx.x, lane = tid & 31, warp = tid >> 5;
    int g = lane >> 2, q = lane & 3;
    int e0 = blockIdx.x*64, r0 = blockIdx.y*128, wm = warp*16;

    int r8 = tid >> 3, seg = tid & 7;
    const char* srcA = (const char*)g_at + (size_t)r0*(EE/2)*4;
    const char* srcB = (const char*)g_wo + (size_t)e0*(EE/2)*4;

    {
        uint32_t base = smb;
        #pragma unroll
        for (int t = 0; t < 4; ++t) {
            int row = r8 + 32*t;
            int sc = (seg ^ (row & 7))*16;
            CPA16(base + row*128 + seg*16, srcA + ((size_t)row*(EE/2))*4 + sc);
        }
        #pragma unroll
        for (int t = 0; t < 2; ++t) {
            int row = r8 + 32*t;
            int sc = (seg ^ (row & 7))*16;
            CPA16(base + 16384 + row*128 + seg*16, srcB + ((size_t)row*(EE/2))*4 + sc);
        }
        CPC();
    }

    int u0c = ((2*q) ^ g)*4;
    int u1c = ((2*q + 1) ^ g)*4;
    int ra0 = (wm + g)*32, ra1 = (wm + g + 8)*32;

    float oacc[8][4] = {};

    for (int j = 0; j < 16; ++j) {
        CPW(0);
        __syncthreads();
        if (j + 1 < 16) {
            int kc = (j + 1)*32;
            uint32_t base = smb + ((j + 1) & 1)*OSTG3*4;
            #pragma unroll
            for (int t = 0; t < 4; ++t) {
                int row = r8 + 32*t;
                int sc = (seg ^ (row & 7))*16;
                CPA16(base + row*128 + seg*16, srcA + ((size_t)row*(EE/2) + kc)*4 + sc);
            }
            #pragma unroll
            for (int t = 0; t < 2; ++t) {
                int row = r8 + 32*t;
                int sc = (seg ^ (row & 7))*16;
                CPA16(base + 16384 + row*128 + seg*16, srcB + ((size_t)row*(EE/2) + kc)*4 + sc);
            }
            CPC();
        }

        const uint32_t* As = smo + (j & 1)*OSTG3;
        const uint32_t* Bs = As + 4096;

        uint4 Aa0 = *(const uint4*)&As[ra0 + u0c], Aa1 = *(const uint4*)&As[ra0 + u1c];
        uint4 Ga0 = *(const uint4*)&As[ra1 + u0c], Ga1 = *(const uint4*)&As[ra1 + u1c];

        #pragma unroll
        for (int nb = 0; nb < 8; ++nb) {
            int rb = (8*nb + g)*32;
            uint4 b0 = *(const uint4*)&Bs[rb + u0c];
            uint4 b1 = *(const uint4*)&Bs[rb + u1c];
            mma_f16(oacc[nb], Aa0.x, Ga0.x, Aa0.y, Ga0.y, b0.x, b0.y);
            mma_f16(oacc[nb], Aa0.z, Ga0.z, Aa0.w, Ga0.w, b0.z, b0.w);
            mma_f16(oacc[nb], Aa1.x, Ga1.x, Aa1.y, Ga1.y, b1.x, b1.y);
            mma_f16(oacc[nb], Aa1.z, Ga1.z, Aa1.w, Ga1.w, b1.z, b1.w);
        }
    }

    float* o0 = &out[(size_t)(r0 + wm + g)*EE + e0];
    float* o1 = &out[(size_t)(r0 + wm + g + 8)*EE + e0];
    #pragma unroll
    for (int nb = 0; nb < 8; ++nb) {
        int c = nb*8 + 2*q;
        float b0 = bo[e0 + c], b1 = bo[e0 + c + 1];
        o0[c] = oacc[nb][0] + b0; o0[c+1] = oacc[nb][1] + b1;
        o1[c] = oacc[nb][2] + b0; o1[c+1] = oacc[nb][3] + b1;
    }
}

// ---------------------------------------------------------------------------
extern "C" void kernel_launch(void* const* d_in, const int* in_sizes, int n_in,
                              void* d_out, int out_size)
{
    const float* x    = (const float*)d_in[0];
    const float* mask = (const float*)d_in[1];
    const float* Wq   = (const float*)d_in[2];
    const float* bq   = (const float*)d_in[3];
    const float* Wk   = (const float*)d_in[4];
    const float* bk   = (const float*)d_in[5];
    const float* Wv   = (const float*)d_in[6];
    const float* bv   = (const float*)d_in[7];
    const float* Wo   = (const float*)d_in[8];
    const float* bo   = (const float*)d_in[9];
    float* out = (float*)d_out;

    cudaFuncSetAttribute(qkv_wo_kernel, cudaFuncAttributeMaxDynamicSharedMemorySize, QKV_SMEM_BYTES);
    cudaFuncSetAttribute(attn_kernel,   cudaFuncAttributeMaxDynamicSharedMemorySize, ATTN_SMEM_BYTES);
    cudaFuncSetAttribute(out_kernel,    cudaFuncAttributeMaxDynamicSharedMemorySize, OUT_SMEM_BYTES);

    qkv_wo_kernel<<<768, 256, QKV_SMEM_BYTES>>>(x, Wq, bq, Wk, bk, Wv, bv, Wo);
    attn_kernel<<<dim3(BH, SS/128), 256, ATTN_SMEM_BYTES>>>(mask);
    out_kernel<<<dim3(EE/64, (BB*SS)/128), 256, OUT_SMEM_BYTES>>>(bo, out);
}